// round 1
// baseline (speedup 1.0000x reference)
#include <cuda_runtime.h>
#include <math.h>
#include <stdint.h>

// Problem constants
#define BB 2
#define SS 2048
#define DD 2048
#define HH 16
#define KVH 2
#define HDIM 128
#define II 5504
#define MM (BB*SS)          // 4096
#define NREP (HH/KVH)       // 8

// ---------------- scratch (device globals; allocation-free) ----------------
__device__ float g_h   [MM*DD];        // rmsnorm1 output
__device__ float g_q   [MM*DD];        // q (B,S,H,HD)
__device__ float g_k   [MM*KVH*HDIM];  // k (B,S,KV,HD)
__device__ float g_v   [MM*KVH*HDIM];  // v
__device__ float g_attn[MM*DD];        // attention output (B,S,D)
__device__ float g_h2  [MM*DD];        // x + attn@wo^T
__device__ float g_g   [MM*DD];        // rmsnorm2 output
__device__ float g_gate[MM*II];
__device__ float g_up  [MM*II];

// ---------------- helpers ----------------
__inline__ __device__ float warpReduceSum(float v) {
    #pragma unroll
    for (int m = 16; m; m >>= 1) v += __shfl_xor_sync(0xffffffffu, v, m);
    return v;
}

// ---------------- RMSNorm: out = x * rsqrt(mean(x^2)+eps) * w ----------------
__global__ __launch_bounds__(256) void rmsnorm_kernel(
    const float* __restrict__ x, const float* __restrict__ w, float* __restrict__ out)
{
    int row = blockIdx.x;
    const float4* xr = (const float4*)(x + (size_t)row * DD);
    const float4* wr = (const float4*)w;
    float4 v0 = xr[threadIdx.x];
    float4 v1 = xr[threadIdx.x + 256];
    float s = v0.x*v0.x + v0.y*v0.y + v0.z*v0.z + v0.w*v0.w
            + v1.x*v1.x + v1.y*v1.y + v1.z*v1.z + v1.w*v1.w;
    s = warpReduceSum(s);
    __shared__ float smw[8];
    __shared__ float sinv;
    if ((threadIdx.x & 31) == 0) smw[threadIdx.x >> 5] = s;
    __syncthreads();
    if (threadIdx.x == 0) {
        float t = 0.f;
        #pragma unroll
        for (int i = 0; i < 8; i++) t += smw[i];
        sinv = rsqrtf(t * (1.0f / DD) + 1e-6f);
    }
    __syncthreads();
    float inv = sinv;
    float4 w0 = wr[threadIdx.x], w1 = wr[threadIdx.x + 256];
    float4 o0, o1;
    o0.x = v0.x*inv*w0.x; o0.y = v0.y*inv*w0.y; o0.z = v0.z*inv*w0.z; o0.w = v0.w*inv*w0.w;
    o1.x = v1.x*inv*w1.x; o1.y = v1.y*inv*w1.y; o1.z = v1.z*inv*w1.z; o1.w = v1.w*inv*w1.w;
    float4* orow = (float4*)(out + (size_t)row * DD);
    orow[threadIdx.x] = o0;
    orow[threadIdx.x + 256] = o1;
}

// ---------------- SGEMM: C = A(MxK) @ B(NxK)^T [+bias | +residual] ----------------
// MODE 0: plain, MODE 1: +bias[col] (aux len N), MODE 2: +aux[row*N+col]
template<int MODE>
__global__ __launch_bounds__(256) void sgemm_kernel(
    const float* __restrict__ A, const float* __restrict__ Bw,
    const float* __restrict__ aux, float* __restrict__ C,
    int M, int N, int K)
{
    __shared__ float As[16][132];
    __shared__ float Bs[16][132];
    const int tid = threadIdx.x;
    const int tx = tid & 15, ty = tid >> 4;
    const int bn = blockIdx.x, bm = blockIdx.y;
    const float* Ab = A  + (size_t)bm * 128 * K;
    const float* Bb = Bw + (size_t)bn * 128 * K;

    float acc[8][8];
    #pragma unroll
    for (int i = 0; i < 8; i++)
        #pragma unroll
        for (int j = 0; j < 8; j++) acc[i][j] = 0.f;

    for (int kt = 0; kt < K; kt += 16) {
        #pragma unroll
        for (int u = 0; u < 2; u++) {
            int f = tid + u * 256;          // 0..511
            int r = f >> 2, c4 = f & 3;     // row 0..127, float4 slot 0..3
            float4 av = *(const float4*)(Ab + (size_t)r * K + kt + c4 * 4);
            As[c4*4+0][r] = av.x; As[c4*4+1][r] = av.y;
            As[c4*4+2][r] = av.z; As[c4*4+3][r] = av.w;
            float4 bv = *(const float4*)(Bb + (size_t)r * K + kt + c4 * 4);
            Bs[c4*4+0][r] = bv.x; Bs[c4*4+1][r] = bv.y;
            Bs[c4*4+2][r] = bv.z; Bs[c4*4+3][r] = bv.w;
        }
        __syncthreads();
        #pragma unroll
        for (int kk = 0; kk < 16; kk++) {
            float a[8], b[8];
            *(float4*)&a[0] = *(const float4*)&As[kk][ty*8];
            *(float4*)&a[4] = *(const float4*)&As[kk][ty*8+4];
            *(float4*)&b[0] = *(const float4*)&Bs[kk][tx*8];
            *(float4*)&b[4] = *(const float4*)&Bs[kk][tx*8+4];
            #pragma unroll
            for (int i = 0; i < 8; i++)
                #pragma unroll
                for (int j = 0; j < 8; j++)
                    acc[i][j] += a[i] * b[j];
        }
        __syncthreads();
    }

    #pragma unroll
    for (int i = 0; i < 8; i++) {
        int row = bm * 128 + ty * 8 + i;
        int col0 = bn * 128 + tx * 8;
        float* Cp = C + (size_t)row * N + col0;
        #pragma unroll
        for (int j = 0; j < 8; j++) {
            float v = acc[i][j];
            if (MODE == 1) v += aux[col0 + j];
            if (MODE == 2) v += aux[(size_t)row * N + col0 + j];
            Cp[j] = v;
        }
    }
}

// ---------------- RoPE (in place): buf is (M, nh, HD) ----------------
__global__ __launch_bounds__(256) void rope_kernel(float* __restrict__ buf, int nh)
{
    int idx = blockIdx.x * 256 + threadIdx.x;     // one thread per (m, head, d<64)
    int d   = idx & 63;
    int t   = idx >> 6;
    int hh  = t % nh;
    int m   = t / nh;
    int pos = m & (SS - 1);
    float inv = powf(10000.0f, -(float)d * (1.0f / 64.0f));
    float fr  = (float)pos * inv;
    float c, sn;
    sincosf(fr, &sn, &c);
    float* p = buf + ((size_t)m * nh + hh) * HDIM + d;
    float x1 = p[0], x2 = p[64];
    p[0]  = x1 * c - x2 * sn;
    p[64] = x2 * c + x1 * sn;
}

// ---------------- Flash attention (causal, GQA) ----------------
// grid (S/64, B*H), 256 threads. Q tile 64x128, iterate K/V tiles of 64.
#define FA_SMEM_FLOATS (128*65*2 + 64*128 + 64*65)
__global__ __launch_bounds__(256) void flash_attn_kernel(
    const float* __restrict__ Q, const float* __restrict__ Kg,
    const float* __restrict__ Vg, float* __restrict__ O)
{
    extern __shared__ float smf[];
    float* Qst = smf;                 // [128][65] transposed: Qst[d*65 + r]
    float* Kst = Qst + 128*65;        // [128][65]
    float* Vs  = Kst + 128*65;        // [64][128]
    float* Ps  = Vs  + 64*128;        // [64][65]

    const int qt = blockIdx.x, bh = blockIdx.y;
    const int b = bh >> 4, h = bh & 15, kvh = h >> 3;
    const int tid = threadIdx.x, tx = tid & 15, ty = tid >> 4;
    const float scale = 0.088388347648318447f;   // 1/sqrt(128)

    // load Q tile (transposed, pre-scaled)
    for (int f = tid; f < 2048; f += 256) {
        int r = f >> 5, c4 = f & 31;
        const float4 v = ((const float4*)(Q + ((size_t)(b*SS + qt*64 + r) * DD + h * HDIM)))[c4];
        Qst[(c4*4+0)*65 + r] = v.x * scale;
        Qst[(c4*4+1)*65 + r] = v.y * scale;
        Qst[(c4*4+2)*65 + r] = v.z * scale;
        Qst[(c4*4+3)*65 + r] = v.w * scale;
    }
    float acc[4][8], mrow[4], lrow[4];
    #pragma unroll
    for (int i = 0; i < 4; i++) {
        mrow[i] = -1e30f; lrow[i] = 0.f;
        #pragma unroll
        for (int j = 0; j < 8; j++) acc[i][j] = 0.f;
    }
    __syncthreads();

    for (int kt = 0; kt <= qt; kt++) {
        // load K (transposed) and V tiles
        for (int f = tid; f < 2048; f += 256) {
            int r = f >> 5, c4 = f & 31;
            size_t base = ((size_t)(b*SS + kt*64 + r) * (KVH*HDIM) + kvh * HDIM);
            float4 kv = ((const float4*)(Kg + base))[c4];
            Kst[(c4*4+0)*65 + r] = kv.x; Kst[(c4*4+1)*65 + r] = kv.y;
            Kst[(c4*4+2)*65 + r] = kv.z; Kst[(c4*4+3)*65 + r] = kv.w;
            ((float4*)(Vs + r * 128))[c4] = ((const float4*)(Vg + base))[c4];
        }
        __syncthreads();

        // scores: 4x4 per thread over d=128
        float s4[4][4];
        #pragma unroll
        for (int i = 0; i < 4; i++)
            #pragma unroll
            for (int j = 0; j < 4; j++) s4[i][j] = 0.f;
        #pragma unroll 4
        for (int d = 0; d < 128; d++) {
            float a0 = Qst[d*65 + ty*4+0], a1 = Qst[d*65 + ty*4+1];
            float a2 = Qst[d*65 + ty*4+2], a3 = Qst[d*65 + ty*4+3];
            float b0 = Kst[d*65 + tx*4+0], b1 = Kst[d*65 + tx*4+1];
            float b2 = Kst[d*65 + tx*4+2], b3 = Kst[d*65 + tx*4+3];
            s4[0][0] += a0*b0; s4[0][1] += a0*b1; s4[0][2] += a0*b2; s4[0][3] += a0*b3;
            s4[1][0] += a1*b0; s4[1][1] += a1*b1; s4[1][2] += a1*b2; s4[1][3] += a1*b3;
            s4[2][0] += a2*b0; s4[2][1] += a2*b1; s4[2][2] += a2*b2; s4[2][3] += a2*b3;
            s4[3][0] += a3*b0; s4[3][1] += a3*b1; s4[3][2] += a3*b2; s4[3][3] += a3*b3;
        }
        if (kt == qt) {
            #pragma unroll
            for (int i = 0; i < 4; i++)
                #pragma unroll
                for (int j = 0; j < 4; j++)
                    if (ty*4 + i < tx*4 + j) s4[i][j] = -1e30f;
        }
        // online softmax update (row reduction over 16 tx lanes)
        #pragma unroll
        for (int i = 0; i < 4; i++) {
            float tm = fmaxf(fmaxf(s4[i][0], s4[i][1]), fmaxf(s4[i][2], s4[i][3]));
            #pragma unroll
            for (int m = 8; m; m >>= 1) tm = fmaxf(tm, __shfl_xor_sync(0xffffffffu, tm, m));
            float mn   = fmaxf(mrow[i], tm);
            float corr = __expf(mrow[i] - mn);
            float rs = 0.f;
            #pragma unroll
            for (int j = 0; j < 4; j++) { float p = __expf(s4[i][j] - mn); s4[i][j] = p; rs += p; }
            #pragma unroll
            for (int m = 8; m; m >>= 1) rs += __shfl_xor_sync(0xffffffffu, rs, m);
            lrow[i] = lrow[i] * corr + rs;
            mrow[i] = mn;
            #pragma unroll
            for (int j = 0; j < 8; j++) acc[i][j] *= corr;
            #pragma unroll
            for (int j = 0; j < 4; j++) Ps[(ty*4+i)*65 + tx*4+j] = s4[i][j];
        }
        __syncthreads();

        // O += P @ V
        #pragma unroll 2
        for (int jj = 0; jj < 64; jj++) {
            float p0 = Ps[(ty*4+0)*65 + jj], p1 = Ps[(ty*4+1)*65 + jj];
            float p2 = Ps[(ty*4+2)*65 + jj], p3 = Ps[(ty*4+3)*65 + jj];
            const float4 va = ((const float4*)(Vs + jj*128 + tx*8))[0];
            const float4 vb = ((const float4*)(Vs + jj*128 + tx*8))[1];
            acc[0][0] += p0*va.x; acc[0][1] += p0*va.y; acc[0][2] += p0*va.z; acc[0][3] += p0*va.w;
            acc[0][4] += p0*vb.x; acc[0][5] += p0*vb.y; acc[0][6] += p0*vb.z; acc[0][7] += p0*vb.w;
            acc[1][0] += p1*va.x; acc[1][1] += p1*va.y; acc[1][2] += p1*va.z; acc[1][3] += p1*va.w;
            acc[1][4] += p1*vb.x; acc[1][5] += p1*vb.y; acc[1][6] += p1*vb.z; acc[1][7] += p1*vb.w;
            acc[2][0] += p2*va.x; acc[2][1] += p2*va.y; acc[2][2] += p2*va.z; acc[2][3] += p2*va.w;
            acc[2][4] += p2*vb.x; acc[2][5] += p2*vb.y; acc[2][6] += p2*vb.z; acc[2][7] += p2*vb.w;
            acc[3][0] += p3*va.x; acc[3][1] += p3*va.y; acc[3][2] += p3*va.z; acc[3][3] += p3*va.w;
            acc[3][4] += p3*vb.x; acc[3][5] += p3*vb.y; acc[3][6] += p3*vb.z; acc[3][7] += p3*vb.w;
        }
        __syncthreads();
    }

    // epilogue: normalize and store to (B,S,H*HD)
    #pragma unroll
    for (int i = 0; i < 4; i++) {
        float inv = 1.0f / lrow[i];
        int srow = qt*64 + ty*4 + i;
        float4 o0, o1;
        o0.x = acc[i][0]*inv; o0.y = acc[i][1]*inv; o0.z = acc[i][2]*inv; o0.w = acc[i][3]*inv;
        o1.x = acc[i][4]*inv; o1.y = acc[i][5]*inv; o1.z = acc[i][6]*inv; o1.w = acc[i][7]*inv;
        float* op = O + ((size_t)(b*SS + srow) * DD + h * HDIM + tx * 8);
        ((float4*)op)[0] = o0;
        ((float4*)op)[1] = o1;
    }
}

// ---------------- silu(gate)*up, in place into gate ----------------
__global__ __launch_bounds__(256) void silu_mul_kernel(
    float* __restrict__ gate, const float* __restrict__ up)
{
    size_t i = (size_t)blockIdx.x * 256 + threadIdx.x;   // float4 index
    float4 g = ((float4*)gate)[i];
    float4 u = ((const float4*)up)[i];
    g.x = g.x / (1.f + __expf(-g.x)) * u.x;
    g.y = g.y / (1.f + __expf(-g.y)) * u.y;
    g.z = g.z / (1.f + __expf(-g.z)) * u.z;
    g.w = g.w / (1.f + __expf(-g.w)) * u.w;
    ((float4*)gate)[i] = g;
}

// ---------------- launch ----------------
extern "C" void kernel_launch(void* const* d_in, const int* in_sizes, int n_in,
                              void* d_out, int out_size)
{
    (void)in_sizes; (void)n_in; (void)out_size;
    const float* x   = (const float*)d_in[0];
    // d_in[1] = mask (causal; applied analytically)
    const float* ln1 = (const float*)d_in[2];
    const float* wq  = (const float*)d_in[3];
    const float* bq  = (const float*)d_in[4];
    const float* wk  = (const float*)d_in[5];
    const float* bk  = (const float*)d_in[6];
    const float* wv  = (const float*)d_in[7];
    const float* bv  = (const float*)d_in[8];
    const float* wo  = (const float*)d_in[9];
    const float* ln2 = (const float*)d_in[10];
    const float* wg  = (const float*)d_in[11];
    const float* wu  = (const float*)d_in[12];
    const float* wd  = (const float*)d_in[13];
    float* out = (float*)d_out;

    float *h, *q, *k, *v, *attn, *h2, *g, *gate, *up;
    cudaGetSymbolAddress((void**)&h,    g_h);
    cudaGetSymbolAddress((void**)&q,    g_q);
    cudaGetSymbolAddress((void**)&k,    g_k);
    cudaGetSymbolAddress((void**)&v,    g_v);
    cudaGetSymbolAddress((void**)&attn, g_attn);
    cudaGetSymbolAddress((void**)&h2,   g_h2);
    cudaGetSymbolAddress((void**)&g,    g_g);
    cudaGetSymbolAddress((void**)&gate, g_gate);
    cudaGetSymbolAddress((void**)&up,   g_up);

    // 1. h = rmsnorm(x, ln1)
    rmsnorm_kernel<<<MM, 256>>>(x, ln1, h);

    // 2. q/k/v projections (+bias)
    sgemm_kernel<1><<<dim3(DD/128, MM/128), 256>>>(h, wq, bq, q, MM, DD, DD);
    sgemm_kernel<1><<<dim3((KVH*HDIM)/128, MM/128), 256>>>(h, wk, bk, k, MM, KVH*HDIM, DD);
    sgemm_kernel<1><<<dim3((KVH*HDIM)/128, MM/128), 256>>>(h, wv, bv, v, MM, KVH*HDIM, DD);

    // 3. RoPE
    rope_kernel<<<(MM*HH*64)/256, 256>>>(q, HH);
    rope_kernel<<<(MM*KVH*64)/256, 256>>>(k, KVH);

    // 4. attention
    const int fa_smem = FA_SMEM_FLOATS * sizeof(float);
    cudaFuncSetAttribute(flash_attn_kernel, cudaFuncAttributeMaxDynamicSharedMemorySize, fa_smem);
    flash_attn_kernel<<<dim3(SS/64, BB*HH), 256, fa_smem>>>(q, k, v, attn);

    // 5. h2 = x + attn @ wo^T
    sgemm_kernel<2><<<dim3(DD/128, MM/128), 256>>>(attn, wo, x, h2, MM, DD, DD);

    // 6. g = rmsnorm(h2, ln2)
    rmsnorm_kernel<<<MM, 256>>>(h2, ln2, g);

    // 7. MLP
    sgemm_kernel<0><<<dim3(II/128, MM/128), 256>>>(g, wg, nullptr, gate, MM, II, DD);
    sgemm_kernel<0><<<dim3(II/128, MM/128), 256>>>(g, wu, nullptr, up,   MM, II, DD);
    silu_mul_kernel<<<(MM*(size_t)II/4)/256, 256>>>(gate, up);

    // 8. out = h2 + act @ wd^T
    sgemm_kernel<2><<<dim3(DD/128, MM/128), 256>>>(gate, wd, h2, out, MM, DD, II);
}

// round 3
// speedup vs baseline: 2.2966x; 2.2966x over previous
#include <cuda_runtime.h>
#include <math.h>
#include <stdint.h>

// Problem constants
#define BB 2
#define SS 2048
#define DD 2048
#define HH 16
#define KVH 2
#define HDIM 128
#define II 5504
#define MM (BB*SS)          // 4096
#define NREP (HH/KVH)       // 8

// ---------------- scratch (device globals; allocation-free) ----------------
__device__ float g_h   [MM*DD];        // rmsnorm1 output (tf32-rounded)
__device__ float g_q   [MM*DD];
__device__ float g_k   [MM*KVH*HDIM];
__device__ float g_v   [MM*KVH*HDIM];
__device__ float g_attn[MM*DD];        // attention output (tf32-rounded)
__device__ float g_h2  [MM*DD];        // x + attn@wo^T (fp32)
__device__ float g_g   [MM*DD];        // rmsnorm2 output (tf32-rounded)
__device__ float g_gate[MM*II];
__device__ float g_up  [MM*II];
// tf32-rounded weight copies
__device__ float g_wq[DD*DD];
__device__ float g_wk[KVH*HDIM*DD];
__device__ float g_wv[KVH*HDIM*DD];
__device__ float g_wo[DD*DD];
__device__ float g_wg[II*DD];
__device__ float g_wu[II*DD];
__device__ float g_wd[DD*II];

// ---------------- small helpers ----------------
__inline__ __device__ float warpReduceSum(float v) {
    #pragma unroll
    for (int m = 16; m; m >>= 1) v += __shfl_xor_sync(0xffffffffu, v, m);
    return v;
}
__device__ __forceinline__ float rna_tf32(float x) {
    uint32_t r;
    asm("cvt.rna.tf32.f32 %0, %1;" : "=r"(r) : "f"(x));
    return __uint_as_float(r);
}
__device__ __forceinline__ uint32_t smem_u32(const void* p) {
    uint32_t a;
    asm("{ .reg .u64 t; cvta.to.shared.u64 t, %1; cvt.u32.u64 %0, t; }" : "=r"(a) : "l"(p));
    return a;
}
__device__ __forceinline__ void cp16(uint32_t s, const void* g) {
    asm volatile("cp.async.cg.shared.global [%0], [%1], 16;" :: "r"(s), "l"(g));
}
__device__ __forceinline__ void cp_commit() {
    asm volatile("cp.async.commit_group;" ::: "memory");
}
__device__ __forceinline__ void mma_tf32_16n8k8(
    float* c, const uint32_t* a, const uint32_t* b)
{
    asm volatile(
        "mma.sync.aligned.m16n8k8.row.col.f32.tf32.tf32.f32 "
        "{%0,%1,%2,%3}, {%4,%5,%6,%7}, {%8,%9}, {%0,%1,%2,%3};"
        : "+f"(c[0]), "+f"(c[1]), "+f"(c[2]), "+f"(c[3])
        : "r"(a[0]), "r"(a[1]), "r"(a[2]), "r"(a[3]), "r"(b[0]), "r"(b[1]));
}

// ---------------- TF32 mma.sync GEMM: C = A(MxK) @ B(NxK)^T ----------------
// CTA tile 128x128x32, 4-stage cp.async pipeline, warp tile 64x32.
// MODE 0: plain, MODE 1: +bias[col], MODE 2: +aux[row*N+col]
#define GEMM_RPAD   36                    // floats per smem row (pad 32->36)
#define GEMM_TILEF  (128*GEMM_RPAD)       // floats per A (or B) tile: 4608
#define GEMM_STAGEF (2*GEMM_TILEF)        // floats per stage: 9216
#define GEMM_STAGES 4
#define GEMM_SMEM   (GEMM_STAGES*GEMM_STAGEF*4)   // 147456 bytes

template<int MODE>
__global__ __launch_bounds__(256) void tc_gemm_kernel(
    const float* __restrict__ A, const float* __restrict__ Bw,
    const float* __restrict__ aux, float* __restrict__ C,
    int M, int N, int K)
{
    extern __shared__ float smf[];
    const uint32_t sb = smem_u32(smf);
    const int tid  = threadIdx.x;
    const int lane = tid & 31;
    const int wid  = tid >> 5;
    const int wm   = wid >> 2;          // 0..1  (M dir, 64 rows each)
    const int wn   = wid & 3;           // 0..3  (N dir, 32 cols each)
    const int bn = blockIdx.x, bm = blockIdx.y;
    const float* Ab = A  + (size_t)bm * 128 * K;
    const float* Bb = Bw + (size_t)bn * 128 * K;

    const int nk = K >> 5;              // number of 32-wide K chunks

    // per-thread load slots: 4 x 16B for A, 4 x 16B for B per stage
    const int lrow = tid >> 3;          // base row pattern (id>>3 for id=tid+u*256)
    const int lc4  = tid & 7;

    auto load_stage = [&](int stage, int kt) {
        const uint32_t as = sb + (uint32_t)stage * (GEMM_STAGEF * 4);
        const uint32_t bs = as + GEMM_TILEF * 4;
        const float* Asrc = Ab + (size_t)kt * 32;
        const float* Bsrc = Bb + (size_t)kt * 32;
        #pragma unroll
        for (int u = 0; u < 4; u++) {
            int row = lrow + u * 32;
            cp16(as + (uint32_t)(row * (GEMM_RPAD*4) + lc4 * 16),
                 Asrc + (size_t)row * K + lc4 * 4);
            cp16(bs + (uint32_t)(row * (GEMM_RPAD*4) + lc4 * 16),
                 Bsrc + (size_t)row * K + lc4 * 4);
        }
        cp_commit();
    };

    float acc[4][4][4];
    #pragma unroll
    for (int i = 0; i < 4; i++)
        #pragma unroll
        for (int j = 0; j < 4; j++)
            #pragma unroll
            for (int e = 0; e < 4; e++) acc[i][j][e] = 0.f;

    // prefetch 3 stages
    #pragma unroll
    for (int s = 0; s < GEMM_STAGES - 1; s++)
        if (s < nk) load_stage(s, s);

    const int rA = (lane >> 2);         // 0..7
    const int kA = (lane & 3);          // 0..3

    for (int kt = 0; kt < nk; kt++) {
        asm volatile("cp.async.wait_group %0;" :: "n"(GEMM_STAGES - 2) : "memory");
        __syncthreads();
        if (kt + GEMM_STAGES - 1 < nk)
            load_stage((kt + GEMM_STAGES - 1) & (GEMM_STAGES - 1), kt + GEMM_STAGES - 1);

        const float* As = smf + (kt & (GEMM_STAGES - 1)) * GEMM_STAGEF;
        const float* Bs = As + GEMM_TILEF;

        #pragma unroll
        for (int kk = 0; kk < 4; kk++) {
            const int k0 = kk * 8 + kA;
            uint32_t a[4][4], b[4][2];
            #pragma unroll
            for (int mt = 0; mt < 4; mt++) {
                int r = wm * 64 + mt * 16 + rA;
                a[mt][0] = __float_as_uint(As[r * GEMM_RPAD + k0]);
                a[mt][1] = __float_as_uint(As[(r + 8) * GEMM_RPAD + k0]);
                a[mt][2] = __float_as_uint(As[r * GEMM_RPAD + k0 + 4]);
                a[mt][3] = __float_as_uint(As[(r + 8) * GEMM_RPAD + k0 + 4]);
            }
            #pragma unroll
            for (int nt = 0; nt < 4; nt++) {
                int cc = wn * 32 + nt * 8 + rA;
                b[nt][0] = __float_as_uint(Bs[cc * GEMM_RPAD + k0]);
                b[nt][1] = __float_as_uint(Bs[cc * GEMM_RPAD + k0 + 4]);
            }
            #pragma unroll
            for (int mt = 0; mt < 4; mt++)
                #pragma unroll
                for (int nt = 0; nt < 4; nt++)
                    mma_tf32_16n8k8(acc[mt][nt], a[mt], b[nt]);
        }
        __syncthreads();
    }

    // epilogue
    #pragma unroll
    for (int mt = 0; mt < 4; mt++) {
        const int r0 = bm * 128 + wm * 64 + mt * 16 + rA;
        #pragma unroll
        for (int nt = 0; nt < 4; nt++) {
            const int c = bn * 128 + wn * 32 + nt * 8 + (kA << 1);
            float2 v0 = make_float2(acc[mt][nt][0], acc[mt][nt][1]);
            float2 v1 = make_float2(acc[mt][nt][2], acc[mt][nt][3]);
            if (MODE == 1) {
                v0.x += aux[c]; v0.y += aux[c + 1];
                v1.x += aux[c]; v1.y += aux[c + 1];
            } else if (MODE == 2) {
                const float2 a0 = *(const float2*)(aux + (size_t)r0 * N + c);
                const float2 a1 = *(const float2*)(aux + (size_t)(r0 + 8) * N + c);
                v0.x += a0.x; v0.y += a0.y;
                v1.x += a1.x; v1.y += a1.y;
            }
            *(float2*)(C + (size_t)r0 * N + c) = v0;
            *(float2*)(C + (size_t)(r0 + 8) * N + c) = v1;
        }
    }
}

// ---------------- RMSNorm (tf32-round the output) ----------------
template<int ROUND>
__global__ __launch_bounds__(256) void rmsnorm_kernel(
    const float* __restrict__ x, const float* __restrict__ w, float* __restrict__ out)
{
    int row = blockIdx.x;
    const float4* xr = (const float4*)(x + (size_t)row * DD);
    const float4* wr = (const float4*)w;
    float4 v0 = xr[threadIdx.x];
    float4 v1 = xr[threadIdx.x + 256];
    float s = v0.x*v0.x + v0.y*v0.y + v0.z*v0.z + v0.w*v0.w
            + v1.x*v1.x + v1.y*v1.y + v1.z*v1.z + v1.w*v1.w;
    s = warpReduceSum(s);
    __shared__ float smw[8];
    __shared__ float sinv;
    if ((threadIdx.x & 31) == 0) smw[threadIdx.x >> 5] = s;
    __syncthreads();
    if (threadIdx.x == 0) {
        float t = 0.f;
        #pragma unroll
        for (int i = 0; i < 8; i++) t += smw[i];
        sinv = rsqrtf(t * (1.0f / DD) + 1e-6f);
    }
    __syncthreads();
    float inv = sinv;
    float4 w0 = wr[threadIdx.x], w1 = wr[threadIdx.x + 256];
    float4 o0, o1;
    o0.x = v0.x*inv*w0.x; o0.y = v0.y*inv*w0.y; o0.z = v0.z*inv*w0.z; o0.w = v0.w*inv*w0.w;
    o1.x = v1.x*inv*w1.x; o1.y = v1.y*inv*w1.y; o1.z = v1.z*inv*w1.z; o1.w = v1.w*inv*w1.w;
    if (ROUND) {
        o0.x = rna_tf32(o0.x); o0.y = rna_tf32(o0.y); o0.z = rna_tf32(o0.z); o0.w = rna_tf32(o0.w);
        o1.x = rna_tf32(o1.x); o1.y = rna_tf32(o1.y); o1.z = rna_tf32(o1.z); o1.w = rna_tf32(o1.w);
    }
    float4* orow = (float4*)(out + (size_t)row * DD);
    orow[threadIdx.x] = o0;
    orow[threadIdx.x + 256] = o1;
}

// ---------------- weight rounding to tf32 (RNE) ----------------
__global__ __launch_bounds__(256) void round_tf32_kernel(
    const float* __restrict__ in, float* __restrict__ out)
{
    size_t i = (size_t)blockIdx.x * 256 + threadIdx.x;   // float4 index
    float4 v = ((const float4*)in)[i];
    v.x = rna_tf32(v.x); v.y = rna_tf32(v.y); v.z = rna_tf32(v.z); v.w = rna_tf32(v.w);
    ((float4*)out)[i] = v;
}

// ---------------- RoPE (in place): buf is (M, nh, HD) ----------------
__global__ __launch_bounds__(256) void rope_kernel(float* __restrict__ buf, int nh)
{
    int idx = blockIdx.x * 256 + threadIdx.x;
    int d   = idx & 63;
    int t   = idx >> 6;
    int hh  = t % nh;
    int m   = t / nh;
    int pos = m & (SS - 1);
    float inv = powf(10000.0f, -(float)d * (1.0f / 64.0f));
    float fr  = (float)pos * inv;
    float c, sn;
    sincosf(fr, &sn, &c);
    float* p = buf + ((size_t)m * nh + hh) * HDIM + d;
    float x1 = p[0], x2 = p[64];
    p[0]  = x1 * c - x2 * sn;
    p[64] = x2 * c + x1 * sn;
}

// ---------------- Flash attention (causal, GQA), fp32 SIMT ----------------
#define FA_SMEM_FLOATS (128*65*2 + 64*128 + 64*65)
__global__ __launch_bounds__(256) void flash_attn_kernel(
    const float* __restrict__ Q, const float* __restrict__ Kg,
    const float* __restrict__ Vg, float* __restrict__ O)
{
    extern __shared__ float smf[];
    float* Qst = smf;
    float* Kst = Qst + 128*65;
    float* Vs  = Kst + 128*65;
    float* Ps  = Vs  + 64*128;

    const int qt = blockIdx.x, bh = blockIdx.y;
    const int b = bh >> 4, h = bh & 15, kvh = h >> 3;
    const int tid = threadIdx.x, tx = tid & 15, ty = tid >> 4;
    const float scale = 0.088388347648318447f;

    for (int f = tid; f < 2048; f += 256) {
        int r = f >> 5, c4 = f & 31;
        const float4 v = ((const float4*)(Q + ((size_t)(b*SS + qt*64 + r) * DD + h * HDIM)))[c4];
        Qst[(c4*4+0)*65 + r] = v.x * scale;
        Qst[(c4*4+1)*65 + r] = v.y * scale;
        Qst[(c4*4+2)*65 + r] = v.z * scale;
        Qst[(c4*4+3)*65 + r] = v.w * scale;
    }
    float acc[4][8], mrow[4], lrow[4];
    #pragma unroll
    for (int i = 0; i < 4; i++) {
        mrow[i] = -1e30f; lrow[i] = 0.f;
        #pragma unroll
        for (int j = 0; j < 8; j++) acc[i][j] = 0.f;
    }
    __syncthreads();

    for (int kt = 0; kt <= qt; kt++) {
        for (int f = tid; f < 2048; f += 256) {
            int r = f >> 5, c4 = f & 31;
            size_t base = ((size_t)(b*SS + kt*64 + r) * (KVH*HDIM) + kvh * HDIM);
            float4 kv = ((const float4*)(Kg + base))[c4];
            Kst[(c4*4+0)*65 + r] = kv.x; Kst[(c4*4+1)*65 + r] = kv.y;
            Kst[(c4*4+2)*65 + r] = kv.z; Kst[(c4*4+3)*65 + r] = kv.w;
            ((float4*)(Vs + r * 128))[c4] = ((const float4*)(Vg + base))[c4];
        }
        __syncthreads();

        float s4[4][4];
        #pragma unroll
        for (int i = 0; i < 4; i++)
            #pragma unroll
            for (int j = 0; j < 4; j++) s4[i][j] = 0.f;
        #pragma unroll 4
        for (int d = 0; d < 128; d++) {
            float a0 = Qst[d*65 + ty*4+0], a1 = Qst[d*65 + ty*4+1];
            float a2 = Qst[d*65 + ty*4+2], a3 = Qst[d*65 + ty*4+3];
            float b0 = Kst[d*65 + tx*4+0], b1 = Kst[d*65 + tx*4+1];
            float b2 = Kst[d*65 + tx*4+2], b3 = Kst[d*65 + tx*4+3];
            s4[0][0] += a0*b0; s4[0][1] += a0*b1; s4[0][2] += a0*b2; s4[0][3] += a0*b3;
            s4[1][0] += a1*b0; s4[1][1] += a1*b1; s4[1][2] += a1*b2; s4[1][3] += a1*b3;
            s4[2][0] += a2*b0; s4[2][1] += a2*b1; s4[2][2] += a2*b2; s4[2][3] += a2*b3;
            s4[3][0] += a3*b0; s4[3][1] += a3*b1; s4[3][2] += a3*b2; s4[3][3] += a3*b3;
        }
        if (kt == qt) {
            #pragma unroll
            for (int i = 0; i < 4; i++)
                #pragma unroll
                for (int j = 0; j < 4; j++)
                    if (ty*4 + i < tx*4 + j) s4[i][j] = -1e30f;
        }
        #pragma unroll
        for (int i = 0; i < 4; i++) {
            float tm = fmaxf(fmaxf(s4[i][0], s4[i][1]), fmaxf(s4[i][2], s4[i][3]));
            #pragma unroll
            for (int m = 8; m; m >>= 1) tm = fmaxf(tm, __shfl_xor_sync(0xffffffffu, tm, m));
            float mn   = fmaxf(mrow[i], tm);
            float corr = __expf(mrow[i] - mn);
            float rs = 0.f;
            #pragma unroll
            for (int j = 0; j < 4; j++) { float p = __expf(s4[i][j] - mn); s4[i][j] = p; rs += p; }
            #pragma unroll
            for (int m = 8; m; m >>= 1) rs += __shfl_xor_sync(0xffffffffu, rs, m);
            lrow[i] = lrow[i] * corr + rs;
            mrow[i] = mn;
            #pragma unroll
            for (int j = 0; j < 8; j++) acc[i][j] *= corr;
            #pragma unroll
            for (int j = 0; j < 4; j++) Ps[(ty*4+i)*65 + tx*4+j] = s4[i][j];
        }
        __syncthreads();

        #pragma unroll 2
        for (int jj = 0; jj < 64; jj++) {
            float p0 = Ps[(ty*4+0)*65 + jj], p1 = Ps[(ty*4+1)*65 + jj];
            float p2 = Ps[(ty*4+2)*65 + jj], p3 = Ps[(ty*4+3)*65 + jj];
            const float4 va = ((const float4*)(Vs + jj*128 + tx*8))[0];
            const float4 vb = ((const float4*)(Vs + jj*128 + tx*8))[1];
            acc[0][0] += p0*va.x; acc[0][1] += p0*va.y; acc[0][2] += p0*va.z; acc[0][3] += p0*va.w;
            acc[0][4] += p0*vb.x; acc[0][5] += p0*vb.y; acc[0][6] += p0*vb.z; acc[0][7] += p0*vb.w;
            acc[1][0] += p1*va.x; acc[1][1] += p1*va.y; acc[1][2] += p1*va.z; acc[1][3] += p1*va.w;
            acc[1][4] += p1*vb.x; acc[1][5] += p1*vb.y; acc[1][6] += p1*vb.z; acc[1][7] += p1*vb.w;
            acc[2][0] += p2*va.x; acc[2][1] += p2*va.y; acc[2][2] += p2*va.z; acc[2][3] += p2*va.w;
            acc[2][4] += p2*vb.x; acc[2][5] += p2*vb.y; acc[2][6] += p2*vb.z; acc[2][7] += p2*vb.w;
            acc[3][0] += p3*va.x; acc[3][1] += p3*va.y; acc[3][2] += p3*va.z; acc[3][3] += p3*va.w;
            acc[3][4] += p3*vb.x; acc[3][5] += p3*vb.y; acc[3][6] += p3*vb.z; acc[3][7] += p3*vb.w;
        }
        __syncthreads();
    }

    #pragma unroll
    for (int i = 0; i < 4; i++) {
        float inv = 1.0f / lrow[i];
        int srow = qt*64 + ty*4 + i;
        float4 o0, o1;
        o0.x = rna_tf32(acc[i][0]*inv); o0.y = rna_tf32(acc[i][1]*inv);
        o0.z = rna_tf32(acc[i][2]*inv); o0.w = rna_tf32(acc[i][3]*inv);
        o1.x = rna_tf32(acc[i][4]*inv); o1.y = rna_tf32(acc[i][5]*inv);
        o1.z = rna_tf32(acc[i][6]*inv); o1.w = rna_tf32(acc[i][7]*inv);
        float* op = O + ((size_t)(b*SS + srow) * DD + h * HDIM + tx * 8);
        ((float4*)op)[0] = o0;
        ((float4*)op)[1] = o1;
    }
}

// ---------------- silu(gate)*up -> gate (tf32-rounded) ----------------
__global__ __launch_bounds__(256) void silu_mul_kernel(
    float* __restrict__ gate, const float* __restrict__ up)
{
    size_t i = (size_t)blockIdx.x * 256 + threadIdx.x;
    float4 g = ((float4*)gate)[i];
    float4 u = ((const float4*)up)[i];
    g.x = rna_tf32(g.x / (1.f + __expf(-g.x)) * u.x);
    g.y = rna_tf32(g.y / (1.f + __expf(-g.y)) * u.y);
    g.z = rna_tf32(g.z / (1.f + __expf(-g.z)) * u.z);
    g.w = rna_tf32(g.w / (1.f + __expf(-g.w)) * u.w);
    ((float4*)gate)[i] = g;
}

// ---------------- launch ----------------
extern "C" void kernel_launch(void* const* d_in, const int* in_sizes, int n_in,
                              void* d_out, int out_size)
{
    (void)in_sizes; (void)n_in; (void)out_size;
    const float* x   = (const float*)d_in[0];
    const float* ln1 = (const float*)d_in[2];
    const float* wq  = (const float*)d_in[3];
    const float* bq  = (const float*)d_in[4];
    const float* wk  = (const float*)d_in[5];
    const float* bk  = (const float*)d_in[6];
    const float* wv  = (const float*)d_in[7];
    const float* bv  = (const float*)d_in[8];
    const float* wo  = (const float*)d_in[9];
    const float* ln2 = (const float*)d_in[10];
    const float* wg  = (const float*)d_in[11];
    const float* wu  = (const float*)d_in[12];
    const float* wd  = (const float*)d_in[13];
    float* out = (float*)d_out;

    float *h, *q, *k, *v, *attn, *h2, *g, *gate, *up;
    float *rwq, *rwk, *rwv, *rwo, *rwg, *rwu, *rwd;
    cudaGetSymbolAddress((void**)&h,    g_h);
    cudaGetSymbolAddress((void**)&q,    g_q);
    cudaGetSymbolAddress((void**)&k,    g_k);
    cudaGetSymbolAddress((void**)&v,    g_v);
    cudaGetSymbolAddress((void**)&attn, g_attn);
    cudaGetSymbolAddress((void**)&h2,   g_h2);
    cudaGetSymbolAddress((void**)&g,    g_g);
    cudaGetSymbolAddress((void**)&gate, g_gate);
    cudaGetSymbolAddress((void**)&up,   g_up);
    cudaGetSymbolAddress((void**)&rwq,  g_wq);
    cudaGetSymbolAddress((void**)&rwk,  g_wk);
    cudaGetSymbolAddress((void**)&rwv,  g_wv);
    cudaGetSymbolAddress((void**)&rwo,  g_wo);
    cudaGetSymbolAddress((void**)&rwg,  g_wg);
    cudaGetSymbolAddress((void**)&rwu,  g_wu);
    cudaGetSymbolAddress((void**)&rwd,  g_wd);

    cudaFuncSetAttribute(tc_gemm_kernel<0>, cudaFuncAttributeMaxDynamicSharedMemorySize, GEMM_SMEM);
    cudaFuncSetAttribute(tc_gemm_kernel<1>, cudaFuncAttributeMaxDynamicSharedMemorySize, GEMM_SMEM);
    cudaFuncSetAttribute(tc_gemm_kernel<2>, cudaFuncAttributeMaxDynamicSharedMemorySize, GEMM_SMEM);

    // 0. round weights to tf32 (RNE)
    round_tf32_kernel<<<(DD*DD/4)/256, 256>>>(wq, rwq);
    round_tf32_kernel<<<(KVH*HDIM*DD/4)/256, 256>>>(wk, rwk);
    round_tf32_kernel<<<(KVH*HDIM*DD/4)/256, 256>>>(wv, rwv);
    round_tf32_kernel<<<(DD*DD/4)/256, 256>>>(wo, rwo);
    round_tf32_kernel<<<(II*DD/4)/256, 256>>>(wg, rwg);
    round_tf32_kernel<<<(II*DD/4)/256, 256>>>(wu, rwu);
    round_tf32_kernel<<<(DD*II/4)/256, 256>>>(wd, rwd);

    // 1. h = round(rmsnorm(x, ln1))
    rmsnorm_kernel<1><<<MM, 256>>>(x, ln1, h);

    // 2. q/k/v projections (+bias), tf32 mma.sync
    tc_gemm_kernel<1><<<dim3(DD/128, MM/128), 256, GEMM_SMEM>>>(h, rwq, bq, q, MM, DD, DD);
    tc_gemm_kernel<1><<<dim3((KVH*HDIM)/128, MM/128), 256, GEMM_SMEM>>>(h, rwk, bk, k, MM, KVH*HDIM, DD);
    tc_gemm_kernel<1><<<dim3((KVH*HDIM)/128, MM/128), 256, GEMM_SMEM>>>(h, rwv, bv, v, MM, KVH*HDIM, DD);

    // 3. RoPE (fp32)
    rope_kernel<<<(MM*HH*64)/256, 256>>>(q, HH);
    rope_kernel<<<(MM*KVH*64)/256, 256>>>(k, KVH);

    // 4. attention (fp32 SIMT flash), output rounded to tf32
    const int fa_smem = FA_SMEM_FLOATS * sizeof(float);
    cudaFuncSetAttribute(flash_attn_kernel, cudaFuncAttributeMaxDynamicSharedMemorySize, fa_smem);
    flash_attn_kernel<<<dim3(SS/64, BB*HH), 256, fa_smem>>>(q, k, v, attn);

    // 5. h2 = x + attn @ wo^T
    tc_gemm_kernel<2><<<dim3(DD/128, MM/128), 256, GEMM_SMEM>>>(attn, rwo, x, h2, MM, DD, DD);

    // 6. g = round(rmsnorm(h2, ln2))
    rmsnorm_kernel<1><<<MM, 256>>>(h2, ln2, g);

    // 7. MLP
    tc_gemm_kernel<0><<<dim3(II/128, MM/128), 256, GEMM_SMEM>>>(g, rwg, nullptr, gate, MM, II, DD);
    tc_gemm_kernel<0><<<dim3(II/128, MM/128), 256, GEMM_SMEM>>>(g, rwu, nullptr, up,   MM, II, DD);
    silu_mul_kernel<<<(MM*(size_t)II/4)/256, 256>>>(gate, up);

    // 8. out = h2 + act @ wd^T
    tc_gemm_kernel<2><<<dim3(DD/128, MM/128), 256, GEMM_SMEM>>>(gate, rwd, h2, out, MM, DD, II);
}

// round 4
// speedup vs baseline: 3.0686x; 1.3362x over previous
#include <cuda_runtime.h>
#include <math.h>
#include <stdint.h>

// Problem constants
#define BB 2
#define SS 2048
#define DD 2048
#define HH 16
#define KVH 2
#define HDIM 128
#define II 5504
#define MM (BB*SS)          // 4096
#define NREP (HH/KVH)       // 8

// ---------------- scratch (device globals; allocation-free) ----------------
__device__ float g_h   [MM*DD];
__device__ float g_q   [MM*DD];
__device__ float g_k   [MM*KVH*HDIM];
__device__ float g_v   [MM*KVH*HDIM];
__device__ float g_attn[MM*DD];
__device__ float g_h2  [MM*DD];
__device__ float g_g   [MM*DD];
__device__ float g_gate[MM*II];
__device__ float g_up  [MM*II];
__device__ float g_wq[DD*DD];
__device__ float g_wk[KVH*HDIM*DD];
__device__ float g_wv[KVH*HDIM*DD];
__device__ float g_wo[DD*DD];
__device__ float g_wg[II*DD];
__device__ float g_wu[II*DD];
__device__ float g_wd[DD*II];

// ---------------- small helpers ----------------
__inline__ __device__ float warpReduceSum(float v) {
    #pragma unroll
    for (int m = 16; m; m >>= 1) v += __shfl_xor_sync(0xffffffffu, v, m);
    return v;
}
__device__ __forceinline__ float rna_tf32(float x) {
    uint32_t r;
    asm("cvt.rna.tf32.f32 %0, %1;" : "=r"(r) : "f"(x));
    return __uint_as_float(r);
}
__device__ __forceinline__ uint32_t smem_u32(const void* p) {
    uint32_t a;
    asm("{ .reg .u64 t; cvta.to.shared.u64 t, %1; cvt.u32.u64 %0, t; }" : "=r"(a) : "l"(p));
    return a;
}
__device__ __forceinline__ void cp16(uint32_t s, const void* g) {
    asm volatile("cp.async.cg.shared.global [%0], [%1], 16;" :: "r"(s), "l"(g));
}
__device__ __forceinline__ void cp_commit() {
    asm volatile("cp.async.commit_group;" ::: "memory");
}
__device__ __forceinline__ void mma_tf32_16n8k8(
    float* c, const uint32_t* a, const uint32_t* b)
{
    asm volatile(
        "mma.sync.aligned.m16n8k8.row.col.f32.tf32.tf32.f32 "
        "{%0,%1,%2,%3}, {%4,%5,%6,%7}, {%8,%9}, {%0,%1,%2,%3};"
        : "+f"(c[0]), "+f"(c[1]), "+f"(c[2]), "+f"(c[3])
        : "r"(a[0]), "r"(a[1]), "r"(a[2]), "r"(a[3]), "r"(b[0]), "r"(b[1]));
}

// ---------------- TF32 mma.sync GEMM: C = A(MxK) @ B(NxK)^T ----------------
#define GEMM_RPAD   36
#define GEMM_TILEF  (128*GEMM_RPAD)
#define GEMM_STAGEF (2*GEMM_TILEF)
#define GEMM_STAGES 4
#define GEMM_SMEM   (GEMM_STAGES*GEMM_STAGEF*4)

template<int MODE>
__global__ __launch_bounds__(256) void tc_gemm_kernel(
    const float* __restrict__ A, const float* __restrict__ Bw,
    const float* __restrict__ aux, float* __restrict__ C,
    int M, int N, int K)
{
    extern __shared__ float smf[];
    const uint32_t sb = smem_u32(smf);
    const int tid  = threadIdx.x;
    const int lane = tid & 31;
    const int wid  = tid >> 5;
    const int wm   = wid >> 2;
    const int wn   = wid & 3;
    const int bn = blockIdx.x, bm = blockIdx.y;
    const float* Ab = A  + (size_t)bm * 128 * K;
    const float* Bb = Bw + (size_t)bn * 128 * K;

    const int nk = K >> 5;
    const int lrow = tid >> 3;
    const int lc4  = tid & 7;

    auto load_stage = [&](int stage, int kt) {
        const uint32_t as = sb + (uint32_t)stage * (GEMM_STAGEF * 4);
        const uint32_t bs = as + GEMM_TILEF * 4;
        const float* Asrc = Ab + (size_t)kt * 32;
        const float* Bsrc = Bb + (size_t)kt * 32;
        #pragma unroll
        for (int u = 0; u < 4; u++) {
            int row = lrow + u * 32;
            cp16(as + (uint32_t)(row * (GEMM_RPAD*4) + lc4 * 16),
                 Asrc + (size_t)row * K + lc4 * 4);
            cp16(bs + (uint32_t)(row * (GEMM_RPAD*4) + lc4 * 16),
                 Bsrc + (size_t)row * K + lc4 * 4);
        }
        cp_commit();
    };

    float acc[4][4][4];
    #pragma unroll
    for (int i = 0; i < 4; i++)
        #pragma unroll
        for (int j = 0; j < 4; j++)
            #pragma unroll
            for (int e = 0; e < 4; e++) acc[i][j][e] = 0.f;

    #pragma unroll
    for (int s = 0; s < GEMM_STAGES - 1; s++)
        if (s < nk) load_stage(s, s);

    const int rA = (lane >> 2);
    const int kA = (lane & 3);

    for (int kt = 0; kt < nk; kt++) {
        asm volatile("cp.async.wait_group %0;" :: "n"(GEMM_STAGES - 2) : "memory");
        __syncthreads();
        if (kt + GEMM_STAGES - 1 < nk)
            load_stage((kt + GEMM_STAGES - 1) & (GEMM_STAGES - 1), kt + GEMM_STAGES - 1);

        const float* As = smf + (kt & (GEMM_STAGES - 1)) * GEMM_STAGEF;
        const float* Bs = As + GEMM_TILEF;

        #pragma unroll
        for (int kk = 0; kk < 4; kk++) {
            const int k0 = kk * 8 + kA;
            uint32_t a[4][4], b[4][2];
            #pragma unroll
            for (int mt = 0; mt < 4; mt++) {
                int r = wm * 64 + mt * 16 + rA;
                a[mt][0] = __float_as_uint(As[r * GEMM_RPAD + k0]);
                a[mt][1] = __float_as_uint(As[(r + 8) * GEMM_RPAD + k0]);
                a[mt][2] = __float_as_uint(As[r * GEMM_RPAD + k0 + 4]);
                a[mt][3] = __float_as_uint(As[(r + 8) * GEMM_RPAD + k0 + 4]);
            }
            #pragma unroll
            for (int nt = 0; nt < 4; nt++) {
                int cc = wn * 32 + nt * 8 + rA;
                b[nt][0] = __float_as_uint(Bs[cc * GEMM_RPAD + k0]);
                b[nt][1] = __float_as_uint(Bs[cc * GEMM_RPAD + k0 + 4]);
            }
            #pragma unroll
            for (int mt = 0; mt < 4; mt++)
                #pragma unroll
                for (int nt = 0; nt < 4; nt++)
                    mma_tf32_16n8k8(acc[mt][nt], a[mt], b[nt]);
        }
        __syncthreads();
    }

    #pragma unroll
    for (int mt = 0; mt < 4; mt++) {
        const int r0 = bm * 128 + wm * 64 + mt * 16 + rA;
        #pragma unroll
        for (int nt = 0; nt < 4; nt++) {
            const int c = bn * 128 + wn * 32 + nt * 8 + (kA << 1);
            float2 v0 = make_float2(acc[mt][nt][0], acc[mt][nt][1]);
            float2 v1 = make_float2(acc[mt][nt][2], acc[mt][nt][3]);
            if (MODE == 1) {
                v0.x += aux[c]; v0.y += aux[c + 1];
                v1.x += aux[c]; v1.y += aux[c + 1];
            } else if (MODE == 2) {
                const float2 a0 = *(const float2*)(aux + (size_t)r0 * N + c);
                const float2 a1 = *(const float2*)(aux + (size_t)(r0 + 8) * N + c);
                v0.x += a0.x; v0.y += a0.y;
                v1.x += a1.x; v1.y += a1.y;
            }
            *(float2*)(C + (size_t)r0 * N + c) = v0;
            *(float2*)(C + (size_t)(r0 + 8) * N + c) = v1;
        }
    }
}

// ---------------- RMSNorm (tf32-round the output) ----------------
template<int ROUND>
__global__ __launch_bounds__(256) void rmsnorm_kernel(
    const float* __restrict__ x, const float* __restrict__ w, float* __restrict__ out)
{
    int row = blockIdx.x;
    const float4* xr = (const float4*)(x + (size_t)row * DD);
    const float4* wr = (const float4*)w;
    float4 v0 = xr[threadIdx.x];
    float4 v1 = xr[threadIdx.x + 256];
    float s = v0.x*v0.x + v0.y*v0.y + v0.z*v0.z + v0.w*v0.w
            + v1.x*v1.x + v1.y*v1.y + v1.z*v1.z + v1.w*v1.w;
    s = warpReduceSum(s);
    __shared__ float smw[8];
    __shared__ float sinv;
    if ((threadIdx.x & 31) == 0) smw[threadIdx.x >> 5] = s;
    __syncthreads();
    if (threadIdx.x == 0) {
        float t = 0.f;
        #pragma unroll
        for (int i = 0; i < 8; i++) t += smw[i];
        sinv = rsqrtf(t * (1.0f / DD) + 1e-6f);
    }
    __syncthreads();
    float inv = sinv;
    float4 w0 = wr[threadIdx.x], w1 = wr[threadIdx.x + 256];
    float4 o0, o1;
    o0.x = v0.x*inv*w0.x; o0.y = v0.y*inv*w0.y; o0.z = v0.z*inv*w0.z; o0.w = v0.w*inv*w0.w;
    o1.x = v1.x*inv*w1.x; o1.y = v1.y*inv*w1.y; o1.z = v1.z*inv*w1.z; o1.w = v1.w*inv*w1.w;
    if (ROUND) {
        o0.x = rna_tf32(o0.x); o0.y = rna_tf32(o0.y); o0.z = rna_tf32(o0.z); o0.w = rna_tf32(o0.w);
        o1.x = rna_tf32(o1.x); o1.y = rna_tf32(o1.y); o1.z = rna_tf32(o1.z); o1.w = rna_tf32(o1.w);
    }
    float4* orow = (float4*)(out + (size_t)row * DD);
    orow[threadIdx.x] = o0;
    orow[threadIdx.x + 256] = o1;
}

// ---------------- weight rounding to tf32 (RNE) ----------------
__global__ __launch_bounds__(256) void round_tf32_kernel(
    const float* __restrict__ in, float* __restrict__ out)
{
    size_t i = (size_t)blockIdx.x * 256 + threadIdx.x;
    float4 v = ((const float4*)in)[i];
    v.x = rna_tf32(v.x); v.y = rna_tf32(v.y); v.z = rna_tf32(v.z); v.w = rna_tf32(v.w);
    ((float4*)out)[i] = v;
}

// ---------------- RoPE (in place): buf is (M, nh, HD) ----------------
__global__ __launch_bounds__(256) void rope_kernel(float* __restrict__ buf, int nh)
{
    int idx = blockIdx.x * 256 + threadIdx.x;
    int d   = idx & 63;
    int t   = idx >> 6;
    int hh  = t % nh;
    int m   = t / nh;
    int pos = m & (SS - 1);
    float inv = powf(10000.0f, -(float)d * (1.0f / 64.0f));
    float fr  = (float)pos * inv;
    float c, sn;
    sincosf(fr, &sn, &c);
    float* p = buf + ((size_t)m * nh + hh) * HDIM + d;
    float x1 = p[0], x2 = p[64];
    p[0]  = x1 * c - x2 * sn;
    p[64] = x2 * c + x1 * sn;
}

// ---------------- Flash attention (causal, GQA), tf32 mma.sync ----------------
// Q tile 128 x 128, KV tile 64, 8 warps (16 q rows each).
// Qs[128][132], Ks[64][132], Vs[64][136], Ps[128][68] — all fragment loads
// hit 32 distinct banks: (4r+k)%32 for pad 132/68, (8k+n)%32 for pad 136.
#define FA_QP 132
#define FA_VP 136
#define FA_PP 68
#define FA2_SMEM ((128*FA_QP + 64*FA_QP + 64*FA_VP + 128*FA_PP) * 4)

__global__ __launch_bounds__(256, 1) void flash_mma_kernel(
    const float* __restrict__ Q, const float* __restrict__ Kg,
    const float* __restrict__ Vg, float* __restrict__ O)
{
    extern __shared__ float smf[];
    float* Qs = smf;                    // [128][132]
    float* Ks = Qs + 128*FA_QP;         // [64][132]
    float* Vs = Ks + 64*FA_QP;          // [64][136]
    float* Ps = Vs + 64*FA_VP;          // [128][68]

    const int qt = blockIdx.x, bh = blockIdx.y;
    const int b = bh >> 4, h = bh & 15, kvh = h >> 3;
    const int tid = threadIdx.x, lane = tid & 31, wid = tid >> 5;
    const int gi = lane >> 2, tg = lane & 3;
    const float scale = 0.088388347648318447f;   // 1/sqrt(128)

    // load Q tile (pre-scaled, tf32-rounded)
    for (int f = tid; f < 4096; f += 256) {
        int r = f >> 5, c4 = f & 31;
        float4 v = ((const float4*)(Q + ((size_t)(b*SS + qt*128 + r) * DD + h*HDIM)))[c4];
        v.x = rna_tf32(v.x * scale); v.y = rna_tf32(v.y * scale);
        v.z = rna_tf32(v.z * scale); v.w = rna_tf32(v.w * scale);
        *(float4*)(Qs + r*FA_QP + c4*4) = v;
    }

    float oacc[16][4];
    #pragma unroll
    for (int i = 0; i < 16; i++)
        #pragma unroll
        for (int e = 0; e < 4; e++) oacc[i][e] = 0.f;
    float mrow[2] = {-1e30f, -1e30f}, lrow[2] = {0.f, 0.f};

    const int r0 = wid*16 + gi;
    const int kmax = 2*qt + 2;

    for (int kt = 0; kt < kmax; kt++) {
        __syncthreads();   // prior iteration's smem reads done (also orders Q stores on kt=0)
        for (int f = tid; f < 2048; f += 256) {
            int r = f >> 5, c4 = f & 31;
            size_t base = ((size_t)(b*SS + kt*64 + r) * (KVH*HDIM) + kvh * HDIM);
            float4 kv4 = ((const float4*)(Kg + base))[c4];
            float4 vv4 = ((const float4*)(Vg + base))[c4];
            kv4.x = rna_tf32(kv4.x); kv4.y = rna_tf32(kv4.y);
            kv4.z = rna_tf32(kv4.z); kv4.w = rna_tf32(kv4.w);
            vv4.x = rna_tf32(vv4.x); vv4.y = rna_tf32(vv4.y);
            vv4.z = rna_tf32(vv4.z); vv4.w = rna_tf32(vv4.w);
            *(float4*)(Ks + r*FA_QP + c4*4) = kv4;
            *(float4*)(Vs + r*FA_VP + c4*4) = vv4;
        }
        __syncthreads();

        // fully-masked tile for this warp's rows -> skip
        if (kt*64 > qt*128 + wid*16 + 15) continue;

        // ---- S = Q @ K^T (16 x 64 per warp) ----
        float sa[8][4];
        #pragma unroll
        for (int nt = 0; nt < 8; nt++)
            #pragma unroll
            for (int e = 0; e < 4; e++) sa[nt][e] = 0.f;
        #pragma unroll
        for (int ks = 0; ks < 16; ks++) {
            const float* qp = Qs + r0*FA_QP + ks*8 + tg;
            uint32_t a[4];
            a[0] = __float_as_uint(qp[0]);
            a[1] = __float_as_uint(qp[8*FA_QP]);
            a[2] = __float_as_uint(qp[4]);
            a[3] = __float_as_uint(qp[8*FA_QP + 4]);
            #pragma unroll
            for (int nt = 0; nt < 8; nt++) {
                const float* kp = Ks + (nt*8 + gi)*FA_QP + ks*8 + tg;
                uint32_t bb[2];
                bb[0] = __float_as_uint(kp[0]);
                bb[1] = __float_as_uint(kp[4]);
                mma_tf32_16n8k8(sa[nt], a, bb);
            }
        }

        // ---- causal mask (only diagonal-crossing tiles) ----
        if (kt >= 2*qt) {
            const int qr0 = qt*128 + r0, qr1 = qr0 + 8;
            #pragma unroll
            for (int nt = 0; nt < 8; nt++) {
                int kc = kt*64 + nt*8 + 2*tg;
                if (kc     > qr0) sa[nt][0] = -1e30f;
                if (kc + 1 > qr0) sa[nt][1] = -1e30f;
                if (kc     > qr1) sa[nt][2] = -1e30f;
                if (kc + 1 > qr1) sa[nt][3] = -1e30f;
            }
        }

        // ---- online softmax (rows r0 and r0+8) ----
        float mx0 = -1e30f, mx1 = -1e30f;
        #pragma unroll
        for (int nt = 0; nt < 8; nt++) {
            mx0 = fmaxf(mx0, fmaxf(sa[nt][0], sa[nt][1]));
            mx1 = fmaxf(mx1, fmaxf(sa[nt][2], sa[nt][3]));
        }
        mx0 = fmaxf(mx0, __shfl_xor_sync(0xffffffffu, mx0, 1));
        mx0 = fmaxf(mx0, __shfl_xor_sync(0xffffffffu, mx0, 2));
        mx1 = fmaxf(mx1, __shfl_xor_sync(0xffffffffu, mx1, 1));
        mx1 = fmaxf(mx1, __shfl_xor_sync(0xffffffffu, mx1, 2));
        const float mn0 = fmaxf(mrow[0], mx0), mn1 = fmaxf(mrow[1], mx1);
        const float cr0 = __expf(mrow[0] - mn0), cr1 = __expf(mrow[1] - mn1);
        float s0 = 0.f, s1 = 0.f;
        #pragma unroll
        for (int nt = 0; nt < 8; nt++) {
            float p00 = rna_tf32(__expf(sa[nt][0] - mn0));
            float p01 = rna_tf32(__expf(sa[nt][1] - mn0));
            float p10 = rna_tf32(__expf(sa[nt][2] - mn1));
            float p11 = rna_tf32(__expf(sa[nt][3] - mn1));
            s0 += p00 + p01;
            s1 += p10 + p11;
            *(float2*)(Ps + r0*FA_PP + nt*8 + 2*tg)       = make_float2(p00, p01);
            *(float2*)(Ps + (r0+8)*FA_PP + nt*8 + 2*tg)   = make_float2(p10, p11);
        }
        s0 += __shfl_xor_sync(0xffffffffu, s0, 1);
        s0 += __shfl_xor_sync(0xffffffffu, s0, 2);
        s1 += __shfl_xor_sync(0xffffffffu, s1, 1);
        s1 += __shfl_xor_sync(0xffffffffu, s1, 2);
        lrow[0] = lrow[0]*cr0 + s0;
        lrow[1] = lrow[1]*cr1 + s1;
        mrow[0] = mn0; mrow[1] = mn1;
        #pragma unroll
        for (int nt = 0; nt < 16; nt++) {
            oacc[nt][0] *= cr0; oacc[nt][1] *= cr0;
            oacc[nt][2] *= cr1; oacc[nt][3] *= cr1;
        }
        __syncwarp();

        // ---- O += P @ V (16 x 128 per warp) ----
        #pragma unroll
        for (int ks = 0; ks < 8; ks++) {
            const float* pp = Ps + r0*FA_PP + ks*8 + tg;
            uint32_t a[4];
            a[0] = __float_as_uint(pp[0]);
            a[1] = __float_as_uint(pp[8*FA_PP]);
            a[2] = __float_as_uint(pp[4]);
            a[3] = __float_as_uint(pp[8*FA_PP + 4]);
            #pragma unroll
            for (int nt = 0; nt < 16; nt++) {
                const float* vp = Vs + (ks*8 + tg)*FA_VP + nt*8 + gi;
                uint32_t bb[2];
                bb[0] = __float_as_uint(vp[0]);
                bb[1] = __float_as_uint(vp[4*FA_VP]);
                mma_tf32_16n8k8(oacc[nt], a, bb);
            }
        }
    }

    // ---- epilogue: normalize, round, store ----
    const float inv0 = 1.0f / lrow[0], inv1 = 1.0f / lrow[1];
    float* op0 = O + ((size_t)(b*SS + qt*128 + r0)     * DD + h*HDIM + 2*tg);
    float* op1 = O + ((size_t)(b*SS + qt*128 + r0 + 8) * DD + h*HDIM + 2*tg);
    #pragma unroll
    for (int nt = 0; nt < 16; nt++) {
        *(float2*)(op0 + nt*8) = make_float2(rna_tf32(oacc[nt][0]*inv0),
                                             rna_tf32(oacc[nt][1]*inv0));
        *(float2*)(op1 + nt*8) = make_float2(rna_tf32(oacc[nt][2]*inv1),
                                             rna_tf32(oacc[nt][3]*inv1));
    }
}

// ---------------- silu(gate)*up -> gate (tf32-rounded) ----------------
__global__ __launch_bounds__(256) void silu_mul_kernel(
    float* __restrict__ gate, const float* __restrict__ up)
{
    size_t i = (size_t)blockIdx.x * 256 + threadIdx.x;
    float4 g = ((float4*)gate)[i];
    float4 u = ((const float4*)up)[i];
    g.x = rna_tf32(g.x / (1.f + __expf(-g.x)) * u.x);
    g.y = rna_tf32(g.y / (1.f + __expf(-g.y)) * u.y);
    g.z = rna_tf32(g.z / (1.f + __expf(-g.z)) * u.z);
    g.w = rna_tf32(g.w / (1.f + __expf(-g.w)) * u.w);
    ((float4*)gate)[i] = g;
}

// ---------------- launch ----------------
extern "C" void kernel_launch(void* const* d_in, const int* in_sizes, int n_in,
                              void* d_out, int out_size)
{
    (void)in_sizes; (void)n_in; (void)out_size;
    const float* x   = (const float*)d_in[0];
    const float* ln1 = (const float*)d_in[2];
    const float* wq  = (const float*)d_in[3];
    const float* bq  = (const float*)d_in[4];
    const float* wk  = (const float*)d_in[5];
    const float* bk  = (const float*)d_in[6];
    const float* wv  = (const float*)d_in[7];
    const float* bv  = (const float*)d_in[8];
    const float* wo  = (const float*)d_in[9];
    const float* ln2 = (const float*)d_in[10];
    const float* wg  = (const float*)d_in[11];
    const float* wu  = (const float*)d_in[12];
    const float* wd  = (const float*)d_in[13];
    float* out = (float*)d_out;

    float *h, *q, *k, *v, *attn, *h2, *g, *gate, *up;
    float *rwq, *rwk, *rwv, *rwo, *rwg, *rwu, *rwd;
    cudaGetSymbolAddress((void**)&h,    g_h);
    cudaGetSymbolAddress((void**)&q,    g_q);
    cudaGetSymbolAddress((void**)&k,    g_k);
    cudaGetSymbolAddress((void**)&v,    g_v);
    cudaGetSymbolAddress((void**)&attn, g_attn);
    cudaGetSymbolAddress((void**)&h2,   g_h2);
    cudaGetSymbolAddress((void**)&g,    g_g);
    cudaGetSymbolAddress((void**)&gate, g_gate);
    cudaGetSymbolAddress((void**)&up,   g_up);
    cudaGetSymbolAddress((void**)&rwq,  g_wq);
    cudaGetSymbolAddress((void**)&rwk,  g_wk);
    cudaGetSymbolAddress((void**)&rwv,  g_wv);
    cudaGetSymbolAddress((void**)&rwo,  g_wo);
    cudaGetSymbolAddress((void**)&rwg,  g_wg);
    cudaGetSymbolAddress((void**)&rwu,  g_wu);
    cudaGetSymbolAddress((void**)&rwd,  g_wd);

    cudaFuncSetAttribute(tc_gemm_kernel<0>, cudaFuncAttributeMaxDynamicSharedMemorySize, GEMM_SMEM);
    cudaFuncSetAttribute(tc_gemm_kernel<1>, cudaFuncAttributeMaxDynamicSharedMemorySize, GEMM_SMEM);
    cudaFuncSetAttribute(tc_gemm_kernel<2>, cudaFuncAttributeMaxDynamicSharedMemorySize, GEMM_SMEM);
    cudaFuncSetAttribute(flash_mma_kernel, cudaFuncAttributeMaxDynamicSharedMemorySize, FA2_SMEM);

    // 0. round weights to tf32 (RNE)
    round_tf32_kernel<<<(DD*DD/4)/256, 256>>>(wq, rwq);
    round_tf32_kernel<<<(KVH*HDIM*DD/4)/256, 256>>>(wk, rwk);
    round_tf32_kernel<<<(KVH*HDIM*DD/4)/256, 256>>>(wv, rwv);
    round_tf32_kernel<<<(DD*DD/4)/256, 256>>>(wo, rwo);
    round_tf32_kernel<<<(II*DD/4)/256, 256>>>(wg, rwg);
    round_tf32_kernel<<<(II*DD/4)/256, 256>>>(wu, rwu);
    round_tf32_kernel<<<(DD*II/4)/256, 256>>>(wd, rwd);

    // 1. h = round(rmsnorm(x, ln1))
    rmsnorm_kernel<1><<<MM, 256>>>(x, ln1, h);

    // 2. q/k/v projections (+bias), tf32 mma.sync
    tc_gemm_kernel<1><<<dim3(DD/128, MM/128), 256, GEMM_SMEM>>>(h, rwq, bq, q, MM, DD, DD);
    tc_gemm_kernel<1><<<dim3((KVH*HDIM)/128, MM/128), 256, GEMM_SMEM>>>(h, rwk, bk, k, MM, KVH*HDIM, DD);
    tc_gemm_kernel<1><<<dim3((KVH*HDIM)/128, MM/128), 256, GEMM_SMEM>>>(h, rwv, bv, v, MM, KVH*HDIM, DD);

    // 3. RoPE (fp32)
    rope_kernel<<<(MM*HH*64)/256, 256>>>(q, HH);
    rope_kernel<<<(MM*KVH*64)/256, 256>>>(k, KVH);

    // 4. attention: tf32 mma flash, output rounded to tf32
    flash_mma_kernel<<<dim3(SS/128, BB*HH), 256, FA2_SMEM>>>(q, k, v, attn);

    // 5. h2 = x + attn @ wo^T
    tc_gemm_kernel<2><<<dim3(DD/128, MM/128), 256, GEMM_SMEM>>>(attn, rwo, x, h2, MM, DD, DD);

    // 6. g = round(rmsnorm(h2, ln2))
    rmsnorm_kernel<1><<<MM, 256>>>(h2, ln2, g);

    // 7. MLP
    tc_gemm_kernel<0><<<dim3(II/128, MM/128), 256, GEMM_SMEM>>>(g, rwg, nullptr, gate, MM, II, DD);
    tc_gemm_kernel<0><<<dim3(II/128, MM/128), 256, GEMM_SMEM>>>(g, rwu, nullptr, up,   MM, II, DD);
    silu_mul_kernel<<<(MM*(size_t)II/4)/256, 256>>>(gate, up);

    // 8. out = h2 + act @ wd^T
    tc_gemm_kernel<2><<<dim3(DD/128, MM/128), 256, GEMM_SMEM>>>(gate, rwd, h2, out, MM, DD, II);
}

// round 5
// speedup vs baseline: 5.6487x; 1.8408x over previous
#include <cuda_runtime.h>
#include <cuda_fp16.h>
#include <math.h>
#include <stdint.h>

// Problem constants
#define BB 2
#define SS 2048
#define DD 2048
#define HH 16
#define KVH 2
#define HDIM 128
#define II 5504
#define MM (BB*SS)          // 4096
#define QKVN 2560           // 2048 q + 256 k + 256 v

// ---------------- scratch (device globals; allocation-free) ----------------
__device__ __half g_h   [MM*DD];          // rmsnorm1 out (half)
__device__ __half g_qkv [MM*QKVN];        // fused qkv proj out
__device__ __half g_attn[MM*DD];          // attention out
__device__ float  g_h2  [MM*DD];          // x + attn@wo^T (fp32)
__device__ __half g_g   [MM*DD];          // rmsnorm2 out
__device__ __half g_gate[MM*II];
__device__ __half g_up  [MM*II];
// fp16 weights
__device__ __half g_wqkv[QKVN*DD];
__device__ __half g_wo[DD*DD];
__device__ __half g_wg[II*DD];
__device__ __half g_wu[II*DD];
__device__ __half g_wd[DD*II];
__device__ float  g_bqkv[QKVN];

// ---------------- small helpers ----------------
__inline__ __device__ float warpReduceSum(float v) {
    #pragma unroll
    for (int m = 16; m; m >>= 1) v += __shfl_xor_sync(0xffffffffu, v, m);
    return v;
}
__device__ __forceinline__ uint32_t smem_u32(const void* p) {
    uint32_t a;
    asm("{ .reg .u64 t; cvta.to.shared.u64 t, %1; cvt.u32.u64 %0, t; }" : "=r"(a) : "l"(p));
    return a;
}
__device__ __forceinline__ void cp16(uint32_t s, const void* g) {
    asm volatile("cp.async.cg.shared.global [%0], [%1], 16;" :: "r"(s), "l"(g));
}
__device__ __forceinline__ void cp_commit() {
    asm volatile("cp.async.commit_group;" ::: "memory");
}
__device__ __forceinline__ void mma_f16(float* c, const uint32_t* a, const uint32_t* b) {
    asm volatile(
        "mma.sync.aligned.m16n8k16.row.col.f32.f16.f16.f32 "
        "{%0,%1,%2,%3}, {%4,%5,%6,%7}, {%8,%9}, {%0,%1,%2,%3};"
        : "+f"(c[0]), "+f"(c[1]), "+f"(c[2]), "+f"(c[3])
        : "r"(a[0]), "r"(a[1]), "r"(a[2]), "r"(a[3]), "r"(b[0]), "r"(b[1]));
}

// ---------------- FP16 mma.sync GEMM: C = A(MxK) @ B(NxK)^T ----------------
// CTA tile 128x128x64(halves), 4 stages, warp tile 64x32.
// Smem pitch 72 halves (36 words): frag bank = gi*4+tg -> conflict-free.
#define GP        72                       // halves per smem row
#define G_TILE_B  (128*GP*2)               // 18432 bytes per tile
#define G_STAGE_B (2*G_TILE_B)             // 36864
#define G_STAGES  4
#define GEMM_SMEM (G_STAGES*G_STAGE_B)     // 147456

// MODE 0: plain->half, MODE 1: +bias[col]->half, MODE 2: +aux[row*N+col]->float
template<int MODE, typename CT>
__global__ __launch_bounds__(256) void hgemm_kernel(
    const __half* __restrict__ A, const __half* __restrict__ Bw,
    const float* __restrict__ aux, CT* __restrict__ C,
    int M, int N, int K)
{
    extern __shared__ __half smh[];
    const uint32_t sb = smem_u32(smh);
    const int tid  = threadIdx.x;
    const int lane = tid & 31;
    const int wid  = tid >> 5;
    const int wm   = wid >> 2;
    const int wn   = wid & 3;
    const int gi   = lane >> 2, tg = lane & 3;
    const int bn = blockIdx.x, bm = blockIdx.y;
    const __half* Ab = A  + (size_t)bm * 128 * K;
    const __half* Bb = Bw + (size_t)bn * 128 * K;

    const int nk = K >> 6;                 // 64-half chunks

    auto load_stage = [&](int stage, int kt) {
        const uint32_t as = sb + (uint32_t)stage * G_STAGE_B;
        const uint32_t bs = as + G_TILE_B;
        const __half* Asrc = Ab + (size_t)kt * 64;
        const __half* Bsrc = Bb + (size_t)kt * 64;
        #pragma unroll
        for (int u = 0; u < 4; u++) {
            int f = tid + u * 256;         // 0..1023
            int row = f >> 3, c16 = f & 7;
            cp16(as + (uint32_t)(row * (GP*2) + c16 * 16),
                 Asrc + (size_t)row * K + c16 * 8);
            cp16(bs + (uint32_t)(row * (GP*2) + c16 * 16),
                 Bsrc + (size_t)row * K + c16 * 8);
        }
        cp_commit();
    };

    float acc[4][4][4];
    #pragma unroll
    for (int i = 0; i < 4; i++)
        #pragma unroll
        for (int j = 0; j < 4; j++)
            #pragma unroll
            for (int e = 0; e < 4; e++) acc[i][j][e] = 0.f;

    #pragma unroll
    for (int s = 0; s < G_STAGES - 1; s++)
        if (s < nk) load_stage(s, s);

    for (int kt = 0; kt < nk; kt++) {
        asm volatile("cp.async.wait_group %0;" :: "n"(G_STAGES - 2) : "memory");
        __syncthreads();
        if (kt + G_STAGES - 1 < nk)
            load_stage((kt + G_STAGES - 1) & (G_STAGES - 1), kt + G_STAGES - 1);

        const __half* As = smh + (size_t)(kt & (G_STAGES - 1)) * (G_STAGE_B/2);
        const __half* Bs = As + G_TILE_B/2;

        #pragma unroll
        for (int kk = 0; kk < 4; kk++) {
            const int k0 = kk * 16 + 2*tg;
            uint32_t a[4][4], b[4][2];
            #pragma unroll
            for (int mt = 0; mt < 4; mt++) {
                int r = wm * 64 + mt * 16 + gi;
                a[mt][0] = *(const uint32_t*)(As + r * GP + k0);
                a[mt][1] = *(const uint32_t*)(As + (r + 8) * GP + k0);
                a[mt][2] = *(const uint32_t*)(As + r * GP + k0 + 8);
                a[mt][3] = *(const uint32_t*)(As + (r + 8) * GP + k0 + 8);
            }
            #pragma unroll
            for (int nt = 0; nt < 4; nt++) {
                int cc = wn * 32 + nt * 8 + gi;
                b[nt][0] = *(const uint32_t*)(Bs + cc * GP + k0);
                b[nt][1] = *(const uint32_t*)(Bs + cc * GP + k0 + 8);
            }
            #pragma unroll
            for (int mt = 0; mt < 4; mt++)
                #pragma unroll
                for (int nt = 0; nt < 4; nt++)
                    mma_f16(acc[mt][nt], a[mt], b[nt]);
        }
        __syncthreads();
    }

    // epilogue
    #pragma unroll
    for (int mt = 0; mt < 4; mt++) {
        const int r0 = bm * 128 + wm * 64 + mt * 16 + gi;
        #pragma unroll
        for (int nt = 0; nt < 4; nt++) {
            const int c = bn * 128 + wn * 32 + nt * 8 + 2*tg;
            float v00 = acc[mt][nt][0], v01 = acc[mt][nt][1];
            float v10 = acc[mt][nt][2], v11 = acc[mt][nt][3];
            if (MODE == 1) {
                float bx = aux[c], by = aux[c + 1];
                v00 += bx; v01 += by; v10 += bx; v11 += by;
            }
            if (MODE == 2) {
                const float2 a0 = *(const float2*)(aux + (size_t)r0 * N + c);
                const float2 a1 = *(const float2*)(aux + (size_t)(r0 + 8) * N + c);
                v00 += a0.x; v01 += a0.y; v10 += a1.x; v11 += a1.y;
                *(float2*)((float*)C + (size_t)r0 * N + c) = make_float2(v00, v01);
                *(float2*)((float*)C + (size_t)(r0 + 8) * N + c) = make_float2(v10, v11);
            } else {
                *(__half2*)((__half*)C + (size_t)r0 * N + c) = __floats2half2_rn(v00, v01);
                *(__half2*)((__half*)C + (size_t)(r0 + 8) * N + c) = __floats2half2_rn(v10, v11);
            }
        }
    }
}

// ---------------- RMSNorm: fp32 in -> half out ----------------
__global__ __launch_bounds__(256) void rmsnorm_kernel(
    const float* __restrict__ x, const float* __restrict__ w, __half* __restrict__ out)
{
    int row = blockIdx.x;
    const float4* xr = (const float4*)(x + (size_t)row * DD);
    const float4* wr = (const float4*)w;
    float4 v0 = xr[threadIdx.x];
    float4 v1 = xr[threadIdx.x + 256];
    float s = v0.x*v0.x + v0.y*v0.y + v0.z*v0.z + v0.w*v0.w
            + v1.x*v1.x + v1.y*v1.y + v1.z*v1.z + v1.w*v1.w;
    s = warpReduceSum(s);
    __shared__ float smw[8];
    __shared__ float sinv;
    if ((threadIdx.x & 31) == 0) smw[threadIdx.x >> 5] = s;
    __syncthreads();
    if (threadIdx.x == 0) {
        float t = 0.f;
        #pragma unroll
        for (int i = 0; i < 8; i++) t += smw[i];
        sinv = rsqrtf(t * (1.0f / DD) + 1e-6f);
    }
    __syncthreads();
    float inv = sinv;
    float4 w0 = wr[threadIdx.x], w1 = wr[threadIdx.x + 256];
    __half2* orow = (__half2*)(out + (size_t)row * DD);
    orow[2*threadIdx.x]       = __floats2half2_rn(v0.x*inv*w0.x, v0.y*inv*w0.y);
    orow[2*threadIdx.x + 1]   = __floats2half2_rn(v0.z*inv*w0.z, v0.w*inv*w0.w);
    orow[512 + 2*threadIdx.x] = __floats2half2_rn(v1.x*inv*w1.x, v1.y*inv*w1.y);
    orow[513 + 2*threadIdx.x] = __floats2half2_rn(v1.z*inv*w1.z, v1.w*inv*w1.w);
}

// ---------------- fp32 -> fp16 conversion ----------------
__global__ __launch_bounds__(256) void f2h_kernel(
    const float* __restrict__ in, __half* __restrict__ out)
{
    size_t i = (size_t)blockIdx.x * 256 + threadIdx.x;   // float4 index
    float4 v = ((const float4*)in)[i];
    ((__half2*)out)[2*i]   = __floats2half2_rn(v.x, v.y);
    ((__half2*)out)[2*i+1] = __floats2half2_rn(v.z, v.w);
}

// ---------------- bias concat (q|k|v) ----------------
__global__ void bias_concat_kernel(
    const float* __restrict__ bq, const float* __restrict__ bk,
    const float* __restrict__ bv, float* __restrict__ o)
{
    int i = blockIdx.x * 256 + threadIdx.x;
    if (i < 2048) o[i] = bq[i];
    else if (i < 2304) o[i] = bk[i - 2048];
    else if (i < QKVN) o[i] = bv[i - 2304];
}

// ---------------- RoPE (in place, half): buf row pitch QKVN ----------------
__global__ __launch_bounds__(256) void rope_kernel(
    __half* __restrict__ buf, int nh, int off)
{
    int idx = blockIdx.x * 256 + threadIdx.x;
    int d   = idx & 63;
    int t   = idx >> 6;
    int hh  = t % nh;
    int m   = t / nh;
    int pos = m & (SS - 1);
    float inv = powf(10000.0f, -(float)d * (1.0f / 64.0f));
    float fr  = (float)pos * inv;
    float c, sn;
    sincosf(fr, &sn, &c);
    __half* p = buf + (size_t)m * QKVN + off + hh * HDIM + d;
    float x1 = __half2float(p[0]), x2 = __half2float(p[64]);
    p[0]  = __float2half_rn(x1 * c - x2 * sn);
    p[64] = __float2half_rn(x2 * c + x1 * sn);
}

// ---------------- Flash attention (causal, GQA), fp16 mma ----------------
// Q tile 128x128, KV tile 64, 8 warps x 16 q rows.
// Pitches: Q/K/V 136 halves (68 words), P 72 halves (36 words) — bank-bijective.
#define FQP 136
#define FPP 72
#define FA_SMEM ((128*FQP + 64*FQP + 64*FQP + 128*FPP) * 2)

__global__ __launch_bounds__(256, 1) void flash_mma_kernel(
    const __half* __restrict__ QKV, __half* __restrict__ O)
{
    extern __shared__ __half smh[];
    __half* Qs = smh;                    // [128][136]
    __half* Ks = Qs + 128*FQP;           // [64][136]
    __half* Vs = Ks + 64*FQP;            // [64][136]
    __half* Ps = Vs + 64*FQP;            // [128][72]

    const int qt = blockIdx.x, bh = blockIdx.y;
    const int b = bh >> 4, h = bh & 15, kvh = h >> 3;
    const int tid = threadIdx.x, lane = tid & 31, wid = tid >> 5;
    const int gi = lane >> 2, tg = lane & 3;
    const float scale = 0.088388347648318447f;   // 1/sqrt(128)

    // Q tile: 128 rows x 128 halves
    for (int f = tid; f < 2048; f += 256) {
        int r = f >> 4, c8 = f & 15;
        *(uint4*)(Qs + r*FQP + c8*8) =
            *(const uint4*)(QKV + (size_t)(b*SS + qt*128 + r) * QKVN + h*HDIM + c8*8);
    }

    float oacc[16][4];
    #pragma unroll
    for (int i = 0; i < 16; i++)
        #pragma unroll
        for (int e = 0; e < 4; e++) oacc[i][e] = 0.f;
    float mrow[2] = {-1e30f, -1e30f}, lrow[2] = {0.f, 0.f};

    const int r0 = wid*16 + gi;
    const int kmax = 2*qt + 2;

    for (int kt = 0; kt < kmax; kt++) {
        __syncthreads();
        for (int f = tid; f < 1024; f += 256) {
            int r = f >> 4, c8 = f & 15;
            size_t base = (size_t)(b*SS + kt*64 + r) * QKVN + kvh * HDIM;
            *(uint4*)(Ks + r*FQP + c8*8) = *(const uint4*)(QKV + base + 2048 + c8*8);
            *(uint4*)(Vs + r*FQP + c8*8) = *(const uint4*)(QKV + base + 2304 + c8*8);
        }
        __syncthreads();

        if (kt*64 > qt*128 + wid*16 + 15) continue;

        // ---- S = Q @ K^T ----
        float sa[8][4];
        #pragma unroll
        for (int nt = 0; nt < 8; nt++)
            #pragma unroll
            for (int e = 0; e < 4; e++) sa[nt][e] = 0.f;
        #pragma unroll
        for (int ks = 0; ks < 8; ks++) {
            const int k0 = ks*16 + 2*tg;
            uint32_t a[4];
            a[0] = *(const uint32_t*)(Qs + r0*FQP + k0);
            a[1] = *(const uint32_t*)(Qs + (r0+8)*FQP + k0);
            a[2] = *(const uint32_t*)(Qs + r0*FQP + k0 + 8);
            a[3] = *(const uint32_t*)(Qs + (r0+8)*FQP + k0 + 8);
            #pragma unroll
            for (int nt = 0; nt < 8; nt++) {
                const int n = nt*8 + gi;
                uint32_t bb[2];
                bb[0] = *(const uint32_t*)(Ks + n*FQP + k0);
                bb[1] = *(const uint32_t*)(Ks + n*FQP + k0 + 8);
                mma_f16(sa[nt], a, bb);
            }
        }
        // scale (exact fold) + mask
        #pragma unroll
        for (int nt = 0; nt < 8; nt++)
            #pragma unroll
            for (int e = 0; e < 4; e++) sa[nt][e] *= scale;
        if (kt >= 2*qt) {
            const int qr0 = qt*128 + r0, qr1 = qr0 + 8;
            #pragma unroll
            for (int nt = 0; nt < 8; nt++) {
                int kc = kt*64 + nt*8 + 2*tg;
                if (kc     > qr0) sa[nt][0] = -1e30f;
                if (kc + 1 > qr0) sa[nt][1] = -1e30f;
                if (kc     > qr1) sa[nt][2] = -1e30f;
                if (kc + 1 > qr1) sa[nt][3] = -1e30f;
            }
        }

        // ---- online softmax ----
        float mx0 = -1e30f, mx1 = -1e30f;
        #pragma unroll
        for (int nt = 0; nt < 8; nt++) {
            mx0 = fmaxf(mx0, fmaxf(sa[nt][0], sa[nt][1]));
            mx1 = fmaxf(mx1, fmaxf(sa[nt][2], sa[nt][3]));
        }
        mx0 = fmaxf(mx0, __shfl_xor_sync(0xffffffffu, mx0, 1));
        mx0 = fmaxf(mx0, __shfl_xor_sync(0xffffffffu, mx0, 2));
        mx1 = fmaxf(mx1, __shfl_xor_sync(0xffffffffu, mx1, 1));
        mx1 = fmaxf(mx1, __shfl_xor_sync(0xffffffffu, mx1, 2));
        const float mn0 = fmaxf(mrow[0], mx0), mn1 = fmaxf(mrow[1], mx1);
        const float cr0 = __expf(mrow[0] - mn0), cr1 = __expf(mrow[1] - mn1);
        float s0 = 0.f, s1 = 0.f;
        #pragma unroll
        for (int nt = 0; nt < 8; nt++) {
            __half2 p0 = __floats2half2_rn(__expf(sa[nt][0] - mn0), __expf(sa[nt][1] - mn0));
            __half2 p1 = __floats2half2_rn(__expf(sa[nt][2] - mn1), __expf(sa[nt][3] - mn1));
            float2 p0f = __half22float2(p0), p1f = __half22float2(p1);
            s0 += p0f.x + p0f.y;
            s1 += p1f.x + p1f.y;
            *(__half2*)(Ps + r0*FPP + nt*8 + 2*tg)     = p0;
            *(__half2*)(Ps + (r0+8)*FPP + nt*8 + 2*tg) = p1;
        }
        s0 += __shfl_xor_sync(0xffffffffu, s0, 1);
        s0 += __shfl_xor_sync(0xffffffffu, s0, 2);
        s1 += __shfl_xor_sync(0xffffffffu, s1, 1);
        s1 += __shfl_xor_sync(0xffffffffu, s1, 2);
        lrow[0] = lrow[0]*cr0 + s0;
        lrow[1] = lrow[1]*cr1 + s1;
        mrow[0] = mn0; mrow[1] = mn1;
        #pragma unroll
        for (int nt = 0; nt < 16; nt++) {
            oacc[nt][0] *= cr0; oacc[nt][1] *= cr0;
            oacc[nt][2] *= cr1; oacc[nt][3] *= cr1;
        }
        __syncwarp();

        // ---- O += P @ V ----
        #pragma unroll
        for (int ks = 0; ks < 4; ks++) {
            const int k0 = ks*16 + 2*tg;
            uint32_t a[4];
            a[0] = *(const uint32_t*)(Ps + r0*FPP + k0);
            a[1] = *(const uint32_t*)(Ps + (r0+8)*FPP + k0);
            a[2] = *(const uint32_t*)(Ps + r0*FPP + k0 + 8);
            a[3] = *(const uint32_t*)(Ps + (r0+8)*FPP + k0 + 8);
            #pragma unroll
            for (int ntp = 0; ntp < 8; ntp++) {
                // V^T fragments via ldmatrix.x4.trans
                int kvrow = ks*16 + (lane & 15);
                int dcol  = (ntp*2 + (lane >> 4)) * 8;
                uint32_t addr = smem_u32(Vs + kvrow*FQP + dcol);
                uint32_t b0, b1, b2, b3;
                asm volatile(
                    "ldmatrix.sync.aligned.m8n8.x4.trans.shared.b16 {%0,%1,%2,%3}, [%4];"
                    : "=r"(b0), "=r"(b1), "=r"(b2), "=r"(b3) : "r"(addr));
                uint32_t bb0[2] = {b0, b1}, bb1[2] = {b2, b3};
                mma_f16(oacc[2*ntp],     a, bb0);
                mma_f16(oacc[2*ntp + 1], a, bb1);
            }
        }
    }

    // ---- epilogue ----
    const float inv0 = 1.0f / lrow[0], inv1 = 1.0f / lrow[1];
    __half* op0 = O + (size_t)(b*SS + qt*128 + r0)     * DD + h*HDIM + 2*tg;
    __half* op1 = O + (size_t)(b*SS + qt*128 + r0 + 8) * DD + h*HDIM + 2*tg;
    #pragma unroll
    for (int nt = 0; nt < 16; nt++) {
        *(__half2*)(op0 + nt*8) = __floats2half2_rn(oacc[nt][0]*inv0, oacc[nt][1]*inv0);
        *(__half2*)(op1 + nt*8) = __floats2half2_rn(oacc[nt][2]*inv1, oacc[nt][3]*inv1);
    }
}

// ---------------- silu(gate)*up -> gate (half) ----------------
__global__ __launch_bounds__(256) void silu_mul_kernel(
    __half* __restrict__ gate, const __half* __restrict__ up)
{
    size_t i = (size_t)blockIdx.x * 256 + threadIdx.x;   // 4-half unit
    __half2 g0 = ((const __half2*)gate)[2*i],   g1 = ((const __half2*)gate)[2*i+1];
    __half2 u0 = ((const __half2*)up)[2*i],     u1 = ((const __half2*)up)[2*i+1];
    float2 gf0 = __half22float2(g0), gf1 = __half22float2(g1);
    float2 uf0 = __half22float2(u0), uf1 = __half22float2(u1);
    gf0.x = gf0.x / (1.f + __expf(-gf0.x)) * uf0.x;
    gf0.y = gf0.y / (1.f + __expf(-gf0.y)) * uf0.y;
    gf1.x = gf1.x / (1.f + __expf(-gf1.x)) * uf1.x;
    gf1.y = gf1.y / (1.f + __expf(-gf1.y)) * uf1.y;
    ((__half2*)gate)[2*i]   = __floats2half2_rn(gf0.x, gf0.y);
    ((__half2*)gate)[2*i+1] = __floats2half2_rn(gf1.x, gf1.y);
}

// ---------------- launch ----------------
extern "C" void kernel_launch(void* const* d_in, const int* in_sizes, int n_in,
                              void* d_out, int out_size)
{
    (void)in_sizes; (void)n_in; (void)out_size;
    const float* x   = (const float*)d_in[0];
    const float* ln1 = (const float*)d_in[2];
    const float* wq  = (const float*)d_in[3];
    const float* bq  = (const float*)d_in[4];
    const float* wk  = (const float*)d_in[5];
    const float* bk  = (const float*)d_in[6];
    const float* wv  = (const float*)d_in[7];
    const float* bv  = (const float*)d_in[8];
    const float* wo  = (const float*)d_in[9];
    const float* ln2 = (const float*)d_in[10];
    const float* wg  = (const float*)d_in[11];
    const float* wu  = (const float*)d_in[12];
    const float* wd  = (const float*)d_in[13];
    float* out = (float*)d_out;

    __half *h, *qkv, *attn, *g, *gate, *up;
    __half *rwqkv, *rwo, *rwg, *rwu, *rwd;
    float *h2, *bqkv;
    cudaGetSymbolAddress((void**)&h,     g_h);
    cudaGetSymbolAddress((void**)&qkv,   g_qkv);
    cudaGetSymbolAddress((void**)&attn,  g_attn);
    cudaGetSymbolAddress((void**)&h2,    g_h2);
    cudaGetSymbolAddress((void**)&g,     g_g);
    cudaGetSymbolAddress((void**)&gate,  g_gate);
    cudaGetSymbolAddress((void**)&up,    g_up);
    cudaGetSymbolAddress((void**)&rwqkv, g_wqkv);
    cudaGetSymbolAddress((void**)&rwo,   g_wo);
    cudaGetSymbolAddress((void**)&rwg,   g_wg);
    cudaGetSymbolAddress((void**)&rwu,   g_wu);
    cudaGetSymbolAddress((void**)&rwd,   g_wd);
    cudaGetSymbolAddress((void**)&bqkv,  g_bqkv);

    cudaFuncSetAttribute((const void*)hgemm_kernel<0,__half>, cudaFuncAttributeMaxDynamicSharedMemorySize, GEMM_SMEM);
    cudaFuncSetAttribute((const void*)hgemm_kernel<1,__half>, cudaFuncAttributeMaxDynamicSharedMemorySize, GEMM_SMEM);
    cudaFuncSetAttribute((const void*)hgemm_kernel<2,float>,  cudaFuncAttributeMaxDynamicSharedMemorySize, GEMM_SMEM);
    cudaFuncSetAttribute((const void*)flash_mma_kernel, cudaFuncAttributeMaxDynamicSharedMemorySize, FA_SMEM);

    // 0. weights -> fp16 (wq|wk|wv fused), bias concat
    f2h_kernel<<<(DD*DD/4)/256, 256>>>(wq, rwqkv);
    f2h_kernel<<<(256*DD/4)/256, 256>>>(wk, rwqkv + 2048*DD);
    f2h_kernel<<<(256*DD/4)/256, 256>>>(wv, rwqkv + 2304*DD);
    f2h_kernel<<<(DD*DD/4)/256, 256>>>(wo, rwo);
    f2h_kernel<<<(II*DD/4)/256, 256>>>(wg, rwg);
    f2h_kernel<<<(II*DD/4)/256, 256>>>(wu, rwu);
    f2h_kernel<<<(DD*II/4)/256, 256>>>(wd, rwd);
    bias_concat_kernel<<<10, 256>>>(bq, bk, bv, bqkv);

    // 1. h = rmsnorm(x, ln1) -> half
    rmsnorm_kernel<<<MM, 256>>>(x, ln1, h);

    // 2. fused qkv projection (+bias)
    hgemm_kernel<1,__half><<<dim3(QKVN/128, MM/128), 256, GEMM_SMEM>>>(h, rwqkv, bqkv, qkv, MM, QKVN, DD);

    // 3. RoPE (q at offset 0, k at 2048)
    rope_kernel<<<(MM*HH*64)/256, 256>>>(qkv, HH, 0);
    rope_kernel<<<(MM*KVH*64)/256, 256>>>(qkv, KVH, 2048);

    // 4. attention
    flash_mma_kernel<<<dim3(SS/128, BB*HH), 256, FA_SMEM>>>(qkv, attn);

    // 5. h2 = x + attn @ wo^T (fp32)
    hgemm_kernel<2,float><<<dim3(DD/128, MM/128), 256, GEMM_SMEM>>>(attn, rwo, x, h2, MM, DD, DD);

    // 6. g = rmsnorm(h2, ln2) -> half
    rmsnorm_kernel<<<MM, 256>>>(h2, ln2, g);

    // 7. MLP
    hgemm_kernel<0,__half><<<dim3(II/128, MM/128), 256, GEMM_SMEM>>>(g, rwg, nullptr, gate, MM, II, DD);
    hgemm_kernel<0,__half><<<dim3(II/128, MM/128), 256, GEMM_SMEM>>>(g, rwu, nullptr, up,   MM, II, DD);
    silu_mul_kernel<<<(MM*(size_t)II/4)/256, 256>>>(gate, up);

    // 8. out = h2 + act @ wd^T (fp32)
    hgemm_kernel<2,float><<<dim3(DD/128, MM/128), 256, GEMM_SMEM>>>(gate, rwd, h2, out, MM, DD, II);
}

// round 6
// speedup vs baseline: 6.6426x; 1.1760x over previous
#include <cuda_runtime.h>
#include <cuda_fp16.h>
#include <math.h>
#include <stdint.h>

// Problem constants
#define BB 2
#define SS 2048
#define DD 2048
#define HH 16
#define KVH 2
#define HDIM 128
#define II 5504
#define MM (BB*SS)          // 4096
#define QKVN 2560           // 2048 q + 256 k + 256 v

// ---------------- scratch (device globals; allocation-free) ----------------
__device__ __half g_h   [MM*DD];
__device__ __half g_qkv [MM*QKVN];
__device__ __half g_attn[MM*DD];
__device__ float  g_h2  [MM*DD];
__device__ __half g_g   [MM*DD];
__device__ __half g_gate[MM*II];
__device__ __half g_up  [MM*II];
__device__ __half g_wqkv[QKVN*DD];
__device__ __half g_wo[DD*DD];
__device__ __half g_wg[II*DD];
__device__ __half g_wu[II*DD];
__device__ __half g_wd[DD*II];
__device__ float  g_bqkv[QKVN];

// ---------------- small helpers ----------------
__inline__ __device__ float warpReduceSum(float v) {
    #pragma unroll
    for (int m = 16; m; m >>= 1) v += __shfl_xor_sync(0xffffffffu, v, m);
    return v;
}
__device__ __forceinline__ uint32_t smem_u32(const void* p) {
    uint32_t a;
    asm("{ .reg .u64 t; cvta.to.shared.u64 t, %1; cvt.u32.u64 %0, t; }" : "=r"(a) : "l"(p));
    return a;
}
__device__ __forceinline__ void cp16(uint32_t s, const void* g) {
    asm volatile("cp.async.cg.shared.global [%0], [%1], 16;" :: "r"(s), "l"(g));
}
__device__ __forceinline__ void cp_commit() {
    asm volatile("cp.async.commit_group;" ::: "memory");
}
__device__ __forceinline__ void mma_f16(float* c, const uint32_t* a, const uint32_t* b) {
    asm volatile(
        "mma.sync.aligned.m16n8k16.row.col.f32.f16.f16.f32 "
        "{%0,%1,%2,%3}, {%4,%5,%6,%7}, {%8,%9}, {%0,%1,%2,%3};"
        : "+f"(c[0]), "+f"(c[1]), "+f"(c[2]), "+f"(c[3])
        : "r"(a[0]), "r"(a[1]), "r"(a[2]), "r"(a[3]), "r"(b[0]), "r"(b[1]));
}
__device__ __forceinline__ void ldm_x4(uint32_t* r, uint32_t addr) {
    asm volatile("ldmatrix.sync.aligned.m8n8.x4.shared.b16 {%0,%1,%2,%3}, [%4];"
        : "=r"(r[0]), "=r"(r[1]), "=r"(r[2]), "=r"(r[3]) : "r"(addr));
}

// ---------------- FP16 mma.sync GEMM: C = A(MxK) @ B(NxK)^T ----------------
// CTA tile 256x128x64(halves), warp tile 64x64 (8 warps, 4 in M x 2 in N),
// 3-stage cp.async, ldmatrix.x4 fragment loads, smem pitch 72 halves (144B):
// every 8-address ldmatrix phase hits banks 4r..4r+3 (r=0..7) -> all 32 banks.
#define GPITCH_B  144                          // bytes per 64-half row
#define A_TILE_B  (256*GPITCH_B)               // 36864
#define B_TILE_B  (128*GPITCH_B)               // 18432
#define STAGE_B   (A_TILE_B + B_TILE_B)        // 55296
#define GEMM_SMEM (3*STAGE_B)                  // 165888

// MODE 0: plain->half, MODE 1: +bias[col]->half, MODE 2: +aux[row*N+col]->float
template<int MODE, typename CT>
__global__ __launch_bounds__(256) void hgemm_kernel(
    const __half* __restrict__ A, const __half* __restrict__ Bw,
    const float* __restrict__ aux, CT* __restrict__ C,
    int M, int N, int K)
{
    extern __shared__ __half smh[];
    const uint32_t sb = smem_u32(smh);
    const int tid  = threadIdx.x;
    const int lane = tid & 31;
    const int wid  = tid >> 5;
    const int wm   = wid & 3;            // 0..3 (M, 64 rows each)
    const int wn   = wid >> 2;           // 0..1 (N, 64 cols each)
    const int gi   = lane >> 2, tg = lane & 3;
    const int bn = blockIdx.x, bm = blockIdx.y;
    const __half* Ab = A  + (size_t)bm * 256 * K;
    const __half* Bb = Bw + (size_t)bn * 128 * K;

    const int nk = K >> 6;

    const int lrow = tid >> 3, lc = tid & 7;
    auto load_stage = [&](int stage, int kt) {
        const uint32_t as = sb + (uint32_t)stage * STAGE_B;
        const uint32_t bs = as + A_TILE_B;
        const __half* Asrc = Ab + (size_t)kt * 64;
        const __half* Bsrc = Bb + (size_t)kt * 64;
        #pragma unroll
        for (int u = 0; u < 8; u++) {
            int row = lrow + u * 32;
            cp16(as + (uint32_t)(row * GPITCH_B + lc * 16),
                 Asrc + (size_t)row * K + lc * 8);
        }
        #pragma unroll
        for (int u = 0; u < 4; u++) {
            int row = lrow + u * 32;
            cp16(bs + (uint32_t)(row * GPITCH_B + lc * 16),
                 Bsrc + (size_t)row * K + lc * 8);
        }
        cp_commit();
    };

    float acc[4][8][4];
    #pragma unroll
    for (int i = 0; i < 4; i++)
        #pragma unroll
        for (int j = 0; j < 8; j++)
            #pragma unroll
            for (int e = 0; e < 4; e++) acc[i][j][e] = 0.f;

    load_stage(0, 0);
    if (nk > 1) load_stage(1, 1);

    // ldmatrix per-lane offsets (bytes)
    const uint32_t a_off = (uint32_t)((lane & 15) * GPITCH_B + ((lane >> 4) << 4));
    const uint32_t b_off = (uint32_t)(((lane & 7) + ((lane >> 4) << 3)) * GPITCH_B
                                      + (((lane >> 3) & 1) << 4));

    int rd = 0, wr = 2;
    for (int kt = 0; kt < nk; kt++) {
        asm volatile("cp.async.wait_group 1;" ::: "memory");
        __syncthreads();
        if (kt + 2 < nk) load_stage(wr, kt + 2);

        const uint32_t as = sb + (uint32_t)rd * STAGE_B;
        const uint32_t bs = as + A_TILE_B;
        const uint32_t a_base = as + (uint32_t)(wm * 64) * GPITCH_B + a_off;
        const uint32_t b_base = bs + (uint32_t)(wn * 64) * GPITCH_B + b_off;

        #pragma unroll
        for (int kk = 0; kk < 4; kk++) {
            const uint32_t k0b = kk * 32;    // 16 halves
            uint32_t a[4][4], b[8][2];
            #pragma unroll
            for (int mt = 0; mt < 4; mt++)
                ldm_x4(a[mt], a_base + (uint32_t)(mt * 16) * GPITCH_B + k0b);
            #pragma unroll
            for (int nb = 0; nb < 4; nb++) {
                uint32_t r[4];
                ldm_x4(r, b_base + (uint32_t)(nb * 16) * GPITCH_B + k0b);
                b[2*nb][0] = r[0]; b[2*nb][1] = r[1];
                b[2*nb+1][0] = r[2]; b[2*nb+1][1] = r[3];
            }
            #pragma unroll
            for (int mt = 0; mt < 4; mt++)
                #pragma unroll
                for (int nt = 0; nt < 8; nt++)
                    mma_f16(acc[mt][nt], a[mt], b[nt]);
        }
        rd = (rd == 2) ? 0 : rd + 1;
        wr = (wr == 2) ? 0 : wr + 1;
    }

    // epilogue
    #pragma unroll
    for (int mt = 0; mt < 4; mt++) {
        const int r0 = bm * 256 + wm * 64 + mt * 16 + gi;
        #pragma unroll
        for (int nt = 0; nt < 8; nt++) {
            const int c = bn * 128 + wn * 64 + nt * 8 + 2*tg;
            float v00 = acc[mt][nt][0], v01 = acc[mt][nt][1];
            float v10 = acc[mt][nt][2], v11 = acc[mt][nt][3];
            if (MODE == 1) {
                float bx = aux[c], by = aux[c + 1];
                v00 += bx; v01 += by; v10 += bx; v11 += by;
            }
            if (MODE == 2) {
                const float2 a0 = *(const float2*)(aux + (size_t)r0 * N + c);
                const float2 a1 = *(const float2*)(aux + (size_t)(r0 + 8) * N + c);
                v00 += a0.x; v01 += a0.y; v10 += a1.x; v11 += a1.y;
                *(float2*)((float*)C + (size_t)r0 * N + c) = make_float2(v00, v01);
                *(float2*)((float*)C + (size_t)(r0 + 8) * N + c) = make_float2(v10, v11);
            } else {
                *(__half2*)((__half*)C + (size_t)r0 * N + c) = __floats2half2_rn(v00, v01);
                *(__half2*)((__half*)C + (size_t)(r0 + 8) * N + c) = __floats2half2_rn(v10, v11);
            }
        }
    }
}

// ---------------- RMSNorm: fp32 in -> half out ----------------
__global__ __launch_bounds__(256) void rmsnorm_kernel(
    const float* __restrict__ x, const float* __restrict__ w, __half* __restrict__ out)
{
    int row = blockIdx.x;
    const float4* xr = (const float4*)(x + (size_t)row * DD);
    const float4* wr = (const float4*)w;
    float4 v0 = xr[threadIdx.x];
    float4 v1 = xr[threadIdx.x + 256];
    float s = v0.x*v0.x + v0.y*v0.y + v0.z*v0.z + v0.w*v0.w
            + v1.x*v1.x + v1.y*v1.y + v1.z*v1.z + v1.w*v1.w;
    s = warpReduceSum(s);
    __shared__ float smw[8];
    __shared__ float sinv;
    if ((threadIdx.x & 31) == 0) smw[threadIdx.x >> 5] = s;
    __syncthreads();
    if (threadIdx.x == 0) {
        float t = 0.f;
        #pragma unroll
        for (int i = 0; i < 8; i++) t += smw[i];
        sinv = rsqrtf(t * (1.0f / DD) + 1e-6f);
    }
    __syncthreads();
    float inv = sinv;
    float4 w0 = wr[threadIdx.x], w1 = wr[threadIdx.x + 256];
    __half2* orow = (__half2*)(out + (size_t)row * DD);
    orow[2*threadIdx.x]       = __floats2half2_rn(v0.x*inv*w0.x, v0.y*inv*w0.y);
    orow[2*threadIdx.x + 1]   = __floats2half2_rn(v0.z*inv*w0.z, v0.w*inv*w0.w);
    orow[512 + 2*threadIdx.x] = __floats2half2_rn(v1.x*inv*w1.x, v1.y*inv*w1.y);
    orow[513 + 2*threadIdx.x] = __floats2half2_rn(v1.z*inv*w1.z, v1.w*inv*w1.w);
}

// ---------------- fp32 -> fp16 conversion ----------------
__global__ __launch_bounds__(256) void f2h_kernel(
    const float* __restrict__ in, __half* __restrict__ out)
{
    size_t i = (size_t)blockIdx.x * 256 + threadIdx.x;
    float4 v = ((const float4*)in)[i];
    ((__half2*)out)[2*i]   = __floats2half2_rn(v.x, v.y);
    ((__half2*)out)[2*i+1] = __floats2half2_rn(v.z, v.w);
}

// ---------------- bias concat (q|k|v) ----------------
__global__ void bias_concat_kernel(
    const float* __restrict__ bq, const float* __restrict__ bk,
    const float* __restrict__ bv, float* __restrict__ o)
{
    int i = blockIdx.x * 256 + threadIdx.x;
    if (i < 2048) o[i] = bq[i];
    else if (i < 2304) o[i] = bk[i - 2048];
    else if (i < QKVN) o[i] = bv[i - 2304];
}

// ---------------- RoPE (in place, half): buf row pitch QKVN ----------------
__global__ __launch_bounds__(256) void rope_kernel(
    __half* __restrict__ buf, int nh, int off)
{
    int idx = blockIdx.x * 256 + threadIdx.x;
    int d   = idx & 63;
    int t   = idx >> 6;
    int hh  = t % nh;
    int m   = t / nh;
    int pos = m & (SS - 1);
    float inv = powf(10000.0f, -(float)d * (1.0f / 64.0f));
    float fr  = (float)pos * inv;
    float c, sn;
    sincosf(fr, &sn, &c);
    __half* p = buf + (size_t)m * QKVN + off + hh * HDIM + d;
    float x1 = __half2float(p[0]), x2 = __half2float(p[64]);
    p[0]  = __float2half_rn(x1 * c - x2 * sn);
    p[64] = __float2half_rn(x2 * c + x1 * sn);
}

// ---------------- Flash attention (causal, GQA), fp16 mma ----------------
#define FQP 136
#define FPP 72
#define FA_SMEM ((128*FQP + 64*FQP + 64*FQP + 128*FPP) * 2)

__global__ __launch_bounds__(256, 1) void flash_mma_kernel(
    const __half* __restrict__ QKV, __half* __restrict__ O)
{
    extern __shared__ __half smh[];
    __half* Qs = smh;
    __half* Ks = Qs + 128*FQP;
    __half* Vs = Ks + 64*FQP;
    __half* Ps = Vs + 64*FQP;

    const int qt = blockIdx.x, bh = blockIdx.y;
    const int b = bh >> 4, h = bh & 15, kvh = h >> 3;
    const int tid = threadIdx.x, lane = tid & 31, wid = tid >> 5;
    const int gi = lane >> 2, tg = lane & 3;
    const float scale = 0.088388347648318447f;

    for (int f = tid; f < 2048; f += 256) {
        int r = f >> 4, c8 = f & 15;
        *(uint4*)(Qs + r*FQP + c8*8) =
            *(const uint4*)(QKV + (size_t)(b*SS + qt*128 + r) * QKVN + h*HDIM + c8*8);
    }

    float oacc[16][4];
    #pragma unroll
    for (int i = 0; i < 16; i++)
        #pragma unroll
        for (int e = 0; e < 4; e++) oacc[i][e] = 0.f;
    float mrow[2] = {-1e30f, -1e30f}, lrow[2] = {0.f, 0.f};

    const int r0 = wid*16 + gi;
    const int kmax = 2*qt + 2;

    for (int kt = 0; kt < kmax; kt++) {
        __syncthreads();
        for (int f = tid; f < 1024; f += 256) {
            int r = f >> 4, c8 = f & 15;
            size_t base = (size_t)(b*SS + kt*64 + r) * QKVN + kvh * HDIM;
            *(uint4*)(Ks + r*FQP + c8*8) = *(const uint4*)(QKV + base + 2048 + c8*8);
            *(uint4*)(Vs + r*FQP + c8*8) = *(const uint4*)(QKV + base + 2304 + c8*8);
        }
        __syncthreads();

        if (kt*64 > qt*128 + wid*16 + 15) continue;

        float sa[8][4];
        #pragma unroll
        for (int nt = 0; nt < 8; nt++)
            #pragma unroll
            for (int e = 0; e < 4; e++) sa[nt][e] = 0.f;
        #pragma unroll
        for (int ks = 0; ks < 8; ks++) {
            const int k0 = ks*16 + 2*tg;
            uint32_t a[4];
            a[0] = *(const uint32_t*)(Qs + r0*FQP + k0);
            a[1] = *(const uint32_t*)(Qs + (r0+8)*FQP + k0);
            a[2] = *(const uint32_t*)(Qs + r0*FQP + k0 + 8);
            a[3] = *(const uint32_t*)(Qs + (r0+8)*FQP + k0 + 8);
            #pragma unroll
            for (int nt = 0; nt < 8; nt++) {
                const int n = nt*8 + gi;
                uint32_t bb[2];
                bb[0] = *(const uint32_t*)(Ks + n*FQP + k0);
                bb[1] = *(const uint32_t*)(Ks + n*FQP + k0 + 8);
                mma_f16(sa[nt], a, bb);
            }
        }
        #pragma unroll
        for (int nt = 0; nt < 8; nt++)
            #pragma unroll
            for (int e = 0; e < 4; e++) sa[nt][e] *= scale;
        if (kt >= 2*qt) {
            const int qr0 = qt*128 + r0, qr1 = qr0 + 8;
            #pragma unroll
            for (int nt = 0; nt < 8; nt++) {
                int kc = kt*64 + nt*8 + 2*tg;
                if (kc     > qr0) sa[nt][0] = -1e30f;
                if (kc + 1 > qr0) sa[nt][1] = -1e30f;
                if (kc     > qr1) sa[nt][2] = -1e30f;
                if (kc + 1 > qr1) sa[nt][3] = -1e30f;
            }
        }

        float mx0 = -1e30f, mx1 = -1e30f;
        #pragma unroll
        for (int nt = 0; nt < 8; nt++) {
            mx0 = fmaxf(mx0, fmaxf(sa[nt][0], sa[nt][1]));
            mx1 = fmaxf(mx1, fmaxf(sa[nt][2], sa[nt][3]));
        }
        mx0 = fmaxf(mx0, __shfl_xor_sync(0xffffffffu, mx0, 1));
        mx0 = fmaxf(mx0, __shfl_xor_sync(0xffffffffu, mx0, 2));
        mx1 = fmaxf(mx1, __shfl_xor_sync(0xffffffffu, mx1, 1));
        mx1 = fmaxf(mx1, __shfl_xor_sync(0xffffffffu, mx1, 2));
        const float mn0 = fmaxf(mrow[0], mx0), mn1 = fmaxf(mrow[1], mx1);
        const float cr0 = __expf(mrow[0] - mn0), cr1 = __expf(mrow[1] - mn1);
        float s0 = 0.f, s1 = 0.f;
        #pragma unroll
        for (int nt = 0; nt < 8; nt++) {
            __half2 p0 = __floats2half2_rn(__expf(sa[nt][0] - mn0), __expf(sa[nt][1] - mn0));
            __half2 p1 = __floats2half2_rn(__expf(sa[nt][2] - mn1), __expf(sa[nt][3] - mn1));
            float2 p0f = __half22float2(p0), p1f = __half22float2(p1);
            s0 += p0f.x + p0f.y;
            s1 += p1f.x + p1f.y;
            *(__half2*)(Ps + r0*FPP + nt*8 + 2*tg)     = p0;
            *(__half2*)(Ps + (r0+8)*FPP + nt*8 + 2*tg) = p1;
        }
        s0 += __shfl_xor_sync(0xffffffffu, s0, 1);
        s0 += __shfl_xor_sync(0xffffffffu, s0, 2);
        s1 += __shfl_xor_sync(0xffffffffu, s1, 1);
        s1 += __shfl_xor_sync(0xffffffffu, s1, 2);
        lrow[0] = lrow[0]*cr0 + s0;
        lrow[1] = lrow[1]*cr1 + s1;
        mrow[0] = mn0; mrow[1] = mn1;
        #pragma unroll
        for (int nt = 0; nt < 16; nt++) {
            oacc[nt][0] *= cr0; oacc[nt][1] *= cr0;
            oacc[nt][2] *= cr1; oacc[nt][3] *= cr1;
        }
        __syncwarp();

        #pragma unroll
        for (int ks = 0; ks < 4; ks++) {
            const int k0 = ks*16 + 2*tg;
            uint32_t a[4];
            a[0] = *(const uint32_t*)(Ps + r0*FPP + k0);
            a[1] = *(const uint32_t*)(Ps + (r0+8)*FPP + k0);
            a[2] = *(const uint32_t*)(Ps + r0*FPP + k0 + 8);
            a[3] = *(const uint32_t*)(Ps + (r0+8)*FPP + k0 + 8);
            #pragma unroll
            for (int ntp = 0; ntp < 8; ntp++) {
                int kvrow = ks*16 + (lane & 15);
                int dcol  = (ntp*2 + (lane >> 4)) * 8;
                uint32_t addr = smem_u32(Vs + kvrow*FQP + dcol);
                uint32_t b0, b1, b2, b3;
                asm volatile(
                    "ldmatrix.sync.aligned.m8n8.x4.trans.shared.b16 {%0,%1,%2,%3}, [%4];"
                    : "=r"(b0), "=r"(b1), "=r"(b2), "=r"(b3) : "r"(addr));
                uint32_t bb0[2] = {b0, b1}, bb1[2] = {b2, b3};
                mma_f16(oacc[2*ntp],     a, bb0);
                mma_f16(oacc[2*ntp + 1], a, bb1);
            }
        }
    }

    const float inv0 = 1.0f / lrow[0], inv1 = 1.0f / lrow[1];
    __half* op0 = O + (size_t)(b*SS + qt*128 + r0)     * DD + h*HDIM + 2*tg;
    __half* op1 = O + (size_t)(b*SS + qt*128 + r0 + 8) * DD + h*HDIM + 2*tg;
    #pragma unroll
    for (int nt = 0; nt < 16; nt++) {
        *(__half2*)(op0 + nt*8) = __floats2half2_rn(oacc[nt][0]*inv0, oacc[nt][1]*inv0);
        *(__half2*)(op1 + nt*8) = __floats2half2_rn(oacc[nt][2]*inv1, oacc[nt][3]*inv1);
    }
}

// ---------------- silu(gate)*up -> gate (half) ----------------
__global__ __launch_bounds__(256) void silu_mul_kernel(
    __half* __restrict__ gate, const __half* __restrict__ up)
{
    size_t i = (size_t)blockIdx.x * 256 + threadIdx.x;
    __half2 g0 = ((const __half2*)gate)[2*i],   g1 = ((const __half2*)gate)[2*i+1];
    __half2 u0 = ((const __half2*)up)[2*i],     u1 = ((const __half2*)up)[2*i+1];
    float2 gf0 = __half22float2(g0), gf1 = __half22float2(g1);
    float2 uf0 = __half22float2(u0), uf1 = __half22float2(u1);
    gf0.x = gf0.x / (1.f + __expf(-gf0.x)) * uf0.x;
    gf0.y = gf0.y / (1.f + __expf(-gf0.y)) * uf0.y;
    gf1.x = gf1.x / (1.f + __expf(-gf1.x)) * uf1.x;
    gf1.y = gf1.y / (1.f + __expf(-gf1.y)) * uf1.y;
    ((__half2*)gate)[2*i]   = __floats2half2_rn(gf0.x, gf0.y);
    ((__half2*)gate)[2*i+1] = __floats2half2_rn(gf1.x, gf1.y);
}

// ---------------- launch ----------------
extern "C" void kernel_launch(void* const* d_in, const int* in_sizes, int n_in,
                              void* d_out, int out_size)
{
    (void)in_sizes; (void)n_in; (void)out_size;
    const float* x   = (const float*)d_in[0];
    const float* ln1 = (const float*)d_in[2];
    const float* wq  = (const float*)d_in[3];
    const float* bq  = (const float*)d_in[4];
    const float* wk  = (const float*)d_in[5];
    const float* bk  = (const float*)d_in[6];
    const float* wv  = (const float*)d_in[7];
    const float* bv  = (const float*)d_in[8];
    const float* wo  = (const float*)d_in[9];
    const float* ln2 = (const float*)d_in[10];
    const float* wg  = (const float*)d_in[11];
    const float* wu  = (const float*)d_in[12];
    const float* wd  = (const float*)d_in[13];
    float* out = (float*)d_out;

    __half *h, *qkv, *attn, *g, *gate, *up;
    __half *rwqkv, *rwo, *rwg, *rwu, *rwd;
    float *h2, *bqkv;
    cudaGetSymbolAddress((void**)&h,     g_h);
    cudaGetSymbolAddress((void**)&qkv,   g_qkv);
    cudaGetSymbolAddress((void**)&attn,  g_attn);
    cudaGetSymbolAddress((void**)&h2,    g_h2);
    cudaGetSymbolAddress((void**)&g,     g_g);
    cudaGetSymbolAddress((void**)&gate,  g_gate);
    cudaGetSymbolAddress((void**)&up,    g_up);
    cudaGetSymbolAddress((void**)&rwqkv, g_wqkv);
    cudaGetSymbolAddress((void**)&rwo,   g_wo);
    cudaGetSymbolAddress((void**)&rwg,   g_wg);
    cudaGetSymbolAddress((void**)&rwu,   g_wu);
    cudaGetSymbolAddress((void**)&rwd,   g_wd);
    cudaGetSymbolAddress((void**)&bqkv,  g_bqkv);

    cudaFuncSetAttribute((const void*)hgemm_kernel<0,__half>, cudaFuncAttributeMaxDynamicSharedMemorySize, GEMM_SMEM);
    cudaFuncSetAttribute((const void*)hgemm_kernel<1,__half>, cudaFuncAttributeMaxDynamicSharedMemorySize, GEMM_SMEM);
    cudaFuncSetAttribute((const void*)hgemm_kernel<2,float>,  cudaFuncAttributeMaxDynamicSharedMemorySize, GEMM_SMEM);
    cudaFuncSetAttribute((const void*)flash_mma_kernel, cudaFuncAttributeMaxDynamicSharedMemorySize, FA_SMEM);

    // 0. weights -> fp16 (wq|wk|wv fused), bias concat
    f2h_kernel<<<(DD*DD/4)/256, 256>>>(wq, rwqkv);
    f2h_kernel<<<(256*DD/4)/256, 256>>>(wk, rwqkv + 2048*DD);
    f2h_kernel<<<(256*DD/4)/256, 256>>>(wv, rwqkv + 2304*DD);
    f2h_kernel<<<(DD*DD/4)/256, 256>>>(wo, rwo);
    f2h_kernel<<<(II*DD/4)/256, 256>>>(wg, rwg);
    f2h_kernel<<<(II*DD/4)/256, 256>>>(wu, rwu);
    f2h_kernel<<<(DD*II/4)/256, 256>>>(wd, rwd);
    bias_concat_kernel<<<10, 256>>>(bq, bk, bv, bqkv);

    // 1. h = rmsnorm(x, ln1) -> half
    rmsnorm_kernel<<<MM, 256>>>(x, ln1, h);

    // 2. fused qkv projection (+bias)
    hgemm_kernel<1,__half><<<dim3(QKVN/128, MM/256), 256, GEMM_SMEM>>>(h, rwqkv, bqkv, qkv, MM, QKVN, DD);

    // 3. RoPE (q at offset 0, k at 2048)
    rope_kernel<<<(MM*HH*64)/256, 256>>>(qkv, HH, 0);
    rope_kernel<<<(MM*KVH*64)/256, 256>>>(qkv, KVH, 2048);

    // 4. attention
    flash_mma_kernel<<<dim3(SS/128, BB*HH), 256, FA_SMEM>>>(qkv, attn);

    // 5. h2 = x + attn @ wo^T (fp32)
    hgemm_kernel<2,float><<<dim3(DD/128, MM/256), 256, GEMM_SMEM>>>(attn, rwo, x, h2, MM, DD, DD);

    // 6. g = rmsnorm(h2, ln2) -> half
    rmsnorm_kernel<<<MM, 256>>>(h2, ln2, g);

    // 7. MLP
    hgemm_kernel<0,__half><<<dim3(II/128, MM/256), 256, GEMM_SMEM>>>(g, rwg, nullptr, gate, MM, II, DD);
    hgemm_kernel<0,__half><<<dim3(II/128, MM/256), 256, GEMM_SMEM>>>(g, rwu, nullptr, up,   MM, II, DD);
    silu_mul_kernel<<<(MM*(size_t)II/4)/256, 256>>>(gate, up);

    // 8. out = h2 + act @ wd^T (fp32)
    hgemm_kernel<2,float><<<dim3(DD/128, MM/256), 256, GEMM_SMEM>>>(gate, rwd, h2, out, MM, DD, II);
}

// round 7
// speedup vs baseline: 7.0250x; 1.0576x over previous
#include <cuda_runtime.h>
#include <cuda_fp16.h>
#include <math.h>
#include <stdint.h>

// Problem constants
#define BB 2
#define SS 2048
#define DD 2048
#define HH 16
#define KVH 2
#define HDIM 128
#define II 5504
#define MM (BB*SS)          // 4096
#define QKVN 2560           // 2048 q + 256 k + 256 v

// ---------------- scratch (device globals; allocation-free) ----------------
__device__ __half g_h   [MM*DD];
__device__ __half g_qkv [MM*QKVN];
__device__ __half g_attn[MM*DD];
__device__ float  g_h2  [MM*DD];
__device__ __half g_g   [MM*DD];
__device__ __half g_act [MM*II];          // silu(gate)*up
__device__ __half g_wqkv[QKVN*DD];
__device__ __half g_wo[DD*DD];
__device__ __half g_wgu[2*II*DD];         // interleaved gate/up weights
__device__ __half g_wd[DD*II];
__device__ float  g_bqkv[QKVN];

// ---------------- small helpers ----------------
__inline__ __device__ float warpReduceSum(float v) {
    #pragma unroll
    for (int m = 16; m; m >>= 1) v += __shfl_xor_sync(0xffffffffu, v, m);
    return v;
}
__device__ __forceinline__ uint32_t smem_u32(const void* p) {
    uint32_t a;
    asm("{ .reg .u64 t; cvta.to.shared.u64 t, %1; cvt.u32.u64 %0, t; }" : "=r"(a) : "l"(p));
    return a;
}
__device__ __forceinline__ void cp16(uint32_t s, const void* g) {
    asm volatile("cp.async.cg.shared.global [%0], [%1], 16;" :: "r"(s), "l"(g));
}
__device__ __forceinline__ void cp_commit() {
    asm volatile("cp.async.commit_group;" ::: "memory");
}
__device__ __forceinline__ void mma_f16(float* c, const uint32_t* a, const uint32_t* b) {
    asm volatile(
        "mma.sync.aligned.m16n8k16.row.col.f32.f16.f16.f32 "
        "{%0,%1,%2,%3}, {%4,%5,%6,%7}, {%8,%9}, {%0,%1,%2,%3};"
        : "+f"(c[0]), "+f"(c[1]), "+f"(c[2]), "+f"(c[3])
        : "r"(a[0]), "r"(a[1]), "r"(a[2]), "r"(a[3]), "r"(b[0]), "r"(b[1]));
}
__device__ __forceinline__ void ldm_x4(uint32_t* r, uint32_t addr) {
    asm volatile("ldmatrix.sync.aligned.m8n8.x4.shared.b16 {%0,%1,%2,%3}, [%4];"
        : "=r"(r[0]), "=r"(r[1]), "=r"(r[2]), "=r"(r[3]) : "r"(addr));
}
__device__ __forceinline__ float silu_f(float x) {
    return x / (1.f + __expf(-x));
}

// ---------------- FP16 mma.sync GEMM: C = A(MxK) @ B(NxK)^T ----------------
// CTA tile 256x128x64(halves), warp tile 64x64 (8 warps, 4 M x 2 N),
// 3-stage cp.async, ldmatrix.x4, pitch 72 halves (144B).
#define GPITCH_B  144
#define A_TILE_B  (256*GPITCH_B)
#define B_TILE_B  (128*GPITCH_B)
#define STAGE_B   (A_TILE_B + B_TILE_B)
#define GEMM_SMEM (3*STAGE_B)

// MODE 0: plain->half, MODE 1: +bias[col]->half, MODE 2: +aux[row*N+col]->float,
// MODE 3: silu-fused MLP: B is interleaved gate/up (2*N rows), C[M,N] = silu(g)*u (half)
template<int MODE, typename CT>
__global__ __launch_bounds__(256) void hgemm_kernel(
    const __half* __restrict__ A, const __half* __restrict__ Bw,
    const float* __restrict__ aux, CT* __restrict__ C,
    int M, int N, int K)
{
    extern __shared__ __half smh[];
    const uint32_t sb = smem_u32(smh);
    const int tid  = threadIdx.x;
    const int lane = tid & 31;
    const int wid  = tid >> 5;
    const int wm   = wid & 3;
    const int wn   = wid >> 2;
    const int gi   = lane >> 2, tg = lane & 3;
    const int bn = blockIdx.x, bm = blockIdx.y;
    const __half* Ab = A  + (size_t)bm * 256 * K;
    const __half* Bb = Bw + (size_t)bn * 128 * K;

    const int nk = K >> 6;

    const int lrow = tid >> 3, lc = tid & 7;
    auto load_stage = [&](int stage, int kt) {
        const uint32_t as = sb + (uint32_t)stage * STAGE_B;
        const uint32_t bs = as + A_TILE_B;
        const __half* Asrc = Ab + (size_t)kt * 64;
        const __half* Bsrc = Bb + (size_t)kt * 64;
        #pragma unroll
        for (int u = 0; u < 8; u++) {
            int row = lrow + u * 32;
            cp16(as + (uint32_t)(row * GPITCH_B + lc * 16),
                 Asrc + (size_t)row * K + lc * 8);
        }
        #pragma unroll
        for (int u = 0; u < 4; u++) {
            int row = lrow + u * 32;
            cp16(bs + (uint32_t)(row * GPITCH_B + lc * 16),
                 Bsrc + (size_t)row * K + lc * 8);
        }
        cp_commit();
    };

    float acc[4][8][4];
    #pragma unroll
    for (int i = 0; i < 4; i++)
        #pragma unroll
        for (int j = 0; j < 8; j++)
            #pragma unroll
            for (int e = 0; e < 4; e++) acc[i][j][e] = 0.f;

    load_stage(0, 0);
    if (nk > 1) load_stage(1, 1);

    const uint32_t a_off = (uint32_t)((lane & 15) * GPITCH_B + ((lane >> 4) << 4));
    const uint32_t b_off = (uint32_t)(((lane & 7) + ((lane >> 4) << 3)) * GPITCH_B
                                      + (((lane >> 3) & 1) << 4));

    int rd = 0, wr = 2;
    for (int kt = 0; kt < nk; kt++) {
        asm volatile("cp.async.wait_group 1;" ::: "memory");
        __syncthreads();
        if (kt + 2 < nk) load_stage(wr, kt + 2);

        const uint32_t as = sb + (uint32_t)rd * STAGE_B;
        const uint32_t bs = as + A_TILE_B;
        const uint32_t a_base = as + (uint32_t)(wm * 64) * GPITCH_B + a_off;
        const uint32_t b_base = bs + (uint32_t)(wn * 64) * GPITCH_B + b_off;

        #pragma unroll
        for (int kk = 0; kk < 4; kk++) {
            const uint32_t k0b = kk * 32;
            uint32_t a[4][4], b[8][2];
            #pragma unroll
            for (int mt = 0; mt < 4; mt++)
                ldm_x4(a[mt], a_base + (uint32_t)(mt * 16) * GPITCH_B + k0b);
            #pragma unroll
            for (int nb = 0; nb < 4; nb++) {
                uint32_t r[4];
                ldm_x4(r, b_base + (uint32_t)(nb * 16) * GPITCH_B + k0b);
                b[2*nb][0] = r[0]; b[2*nb][1] = r[1];
                b[2*nb+1][0] = r[2]; b[2*nb+1][1] = r[3];
            }
            #pragma unroll
            for (int mt = 0; mt < 4; mt++)
                #pragma unroll
                for (int nt = 0; nt < 8; nt++)
                    mma_f16(acc[mt][nt], a[mt], b[nt]);
        }
        rd = (rd == 2) ? 0 : rd + 1;
        wr = (wr == 2) ? 0 : wr + 1;
    }

    // epilogue
    if (MODE == 3) {
        // warp wn holds gate (nt 0..3) and up (nt 4..7) for cols j*32..j*32+31
        const int j = bn * 2 + wn;
        #pragma unroll
        for (int mt = 0; mt < 4; mt++) {
            const int r0 = bm * 256 + wm * 64 + mt * 16 + gi;
            #pragma unroll
            for (int jt = 0; jt < 4; jt++) {
                const int c = j * 32 + jt * 8 + 2*tg;
                float a00 = silu_f(acc[mt][jt][0]) * acc[mt][jt+4][0];
                float a01 = silu_f(acc[mt][jt][1]) * acc[mt][jt+4][1];
                float a10 = silu_f(acc[mt][jt][2]) * acc[mt][jt+4][2];
                float a11 = silu_f(acc[mt][jt][3]) * acc[mt][jt+4][3];
                *(__half2*)((__half*)C + (size_t)r0 * N + c) = __floats2half2_rn(a00, a01);
                *(__half2*)((__half*)C + (size_t)(r0 + 8) * N + c) = __floats2half2_rn(a10, a11);
            }
        }
        return;
    }
    #pragma unroll
    for (int mt = 0; mt < 4; mt++) {
        const int r0 = bm * 256 + wm * 64 + mt * 16 + gi;
        #pragma unroll
        for (int nt = 0; nt < 8; nt++) {
            const int c = bn * 128 + wn * 64 + nt * 8 + 2*tg;
            float v00 = acc[mt][nt][0], v01 = acc[mt][nt][1];
            float v10 = acc[mt][nt][2], v11 = acc[mt][nt][3];
            if (MODE == 1) {
                float bx = aux[c], by = aux[c + 1];
                v00 += bx; v01 += by; v10 += bx; v11 += by;
            }
            if (MODE == 2) {
                const float2 a0 = *(const float2*)(aux + (size_t)r0 * N + c);
                const float2 a1 = *(const float2*)(aux + (size_t)(r0 + 8) * N + c);
                v00 += a0.x; v01 += a0.y; v10 += a1.x; v11 += a1.y;
                *(float2*)((float*)C + (size_t)r0 * N + c) = make_float2(v00, v01);
                *(float2*)((float*)C + (size_t)(r0 + 8) * N + c) = make_float2(v10, v11);
            } else {
                *(__half2*)((__half*)C + (size_t)r0 * N + c) = __floats2half2_rn(v00, v01);
                *(__half2*)((__half*)C + (size_t)(r0 + 8) * N + c) = __floats2half2_rn(v10, v11);
            }
        }
    }
}

// ---------------- RMSNorm: fp32 in -> half out ----------------
__global__ __launch_bounds__(256) void rmsnorm_kernel(
    const float* __restrict__ x, const float* __restrict__ w, __half* __restrict__ out)
{
    int row = blockIdx.x;
    const float4* xr = (const float4*)(x + (size_t)row * DD);
    const float4* wr = (const float4*)w;
    float4 v0 = xr[threadIdx.x];
    float4 v1 = xr[threadIdx.x + 256];
    float s = v0.x*v0.x + v0.y*v0.y + v0.z*v0.z + v0.w*v0.w
            + v1.x*v1.x + v1.y*v1.y + v1.z*v1.z + v1.w*v1.w;
    s = warpReduceSum(s);
    __shared__ float smw[8];
    __shared__ float sinv;
    if ((threadIdx.x & 31) == 0) smw[threadIdx.x >> 5] = s;
    __syncthreads();
    if (threadIdx.x == 0) {
        float t = 0.f;
        #pragma unroll
        for (int i = 0; i < 8; i++) t += smw[i];
        sinv = rsqrtf(t * (1.0f / DD) + 1e-6f);
    }
    __syncthreads();
    float inv = sinv;
    float4 w0 = wr[threadIdx.x], w1 = wr[threadIdx.x + 256];
    __half2* orow = (__half2*)(out + (size_t)row * DD);
    orow[2*threadIdx.x]       = __floats2half2_rn(v0.x*inv*w0.x, v0.y*inv*w0.y);
    orow[2*threadIdx.x + 1]   = __floats2half2_rn(v0.z*inv*w0.z, v0.w*inv*w0.w);
    orow[512 + 2*threadIdx.x] = __floats2half2_rn(v1.x*inv*w1.x, v1.y*inv*w1.y);
    orow[513 + 2*threadIdx.x] = __floats2half2_rn(v1.z*inv*w1.z, v1.w*inv*w1.w);
}

// ---------------- fp32 -> fp16 conversion ----------------
__global__ __launch_bounds__(256) void f2h_kernel(
    const float* __restrict__ in, __half* __restrict__ out)
{
    size_t i = (size_t)blockIdx.x * 256 + threadIdx.x;
    float4 v = ((const float4*)in)[i];
    ((__half2*)out)[2*i]   = __floats2half2_rn(v.x, v.y);
    ((__half2*)out)[2*i+1] = __floats2half2_rn(v.z, v.w);
}

// ---------------- gate/up weights -> interleaved fp16 ----------------
// out rows: [64j..64j+31] = wg[32j..32j+31], [64j+32..64j+63] = wu[32j..32j+31]
__global__ __launch_bounds__(256) void f2h_ilv_kernel(
    const float* __restrict__ wg, const float* __restrict__ wu, __half* __restrict__ out)
{
    size_t i = (size_t)blockIdx.x * 256 + threadIdx.x;   // float4 index over II*DD/4
    int c4 = (int)(i % (DD/4));
    int r  = (int)(i / (DD/4));
    int rg = 64*(r >> 5) + (r & 31);
    float4 gv = ((const float4*)wg)[i];
    float4 uv = ((const float4*)wu)[i];
    __half2* og = (__half2*)(out + (size_t)rg * DD + c4*4);
    og[0] = __floats2half2_rn(gv.x, gv.y);
    og[1] = __floats2half2_rn(gv.z, gv.w);
    __half2* ou = (__half2*)(out + (size_t)(rg + 32) * DD + c4*4);
    ou[0] = __floats2half2_rn(uv.x, uv.y);
    ou[1] = __floats2half2_rn(uv.z, uv.w);
}

// ---------------- bias concat (q|k|v) ----------------
__global__ void bias_concat_kernel(
    const float* __restrict__ bq, const float* __restrict__ bk,
    const float* __restrict__ bv, float* __restrict__ o)
{
    int i = blockIdx.x * 256 + threadIdx.x;
    if (i < 2048) o[i] = bq[i];
    else if (i < 2304) o[i] = bk[i - 2048];
    else if (i < QKVN) o[i] = bv[i - 2304];
}

// ---------------- RoPE (in place, half): buf row pitch QKVN ----------------
__global__ __launch_bounds__(256) void rope_kernel(
    __half* __restrict__ buf, int nh, int off)
{
    int idx = blockIdx.x * 256 + threadIdx.x;
    int d   = idx & 63;
    int t   = idx >> 6;
    int hh  = t % nh;
    int m   = t / nh;
    int pos = m & (SS - 1);
    float inv = exp2f(-(float)d * (13.287712379549449f / 64.0f));   // 10000^(-d/64)
    float fr  = (float)pos * inv;
    float c, sn;
    __sincosf(fr, &sn, &c);
    __half* p = buf + (size_t)m * QKVN + off + hh * HDIM + d;
    float x1 = __half2float(p[0]), x2 = __half2float(p[64]);
    p[0]  = __float2half_rn(x1 * c - x2 * sn);
    p[64] = __float2half_rn(x2 * c + x1 * sn);
}

// ---------------- Flash attention (causal, GQA), fp16 mma, cp.async KV ----------------
#define FQP 136
#define FPP 72
#define FA_SMEM ((128*FQP + 4*64*FQP + 128*FPP) * 2)   // Q + 2-stage K/V + P

__global__ __launch_bounds__(256, 1) void flash_mma_kernel(
    const __half* __restrict__ QKV, __half* __restrict__ O)
{
    extern __shared__ __half smh[];
    __half* Qs  = smh;                       // [128][136]
    __half* Kst = Qs + 128*FQP;              // [2][64][136]
    __half* Vst = Kst + 2*64*FQP;            // [2][64][136]
    __half* Ps  = Vst + 2*64*FQP;            // [128][72]
    const uint32_t sbK = smem_u32(Kst);
    const uint32_t sbV = smem_u32(Vst);

    const int qt = blockIdx.x, bh = blockIdx.y;
    const int b = bh >> 4, h = bh & 15, kvh = h >> 3;
    const int tid = threadIdx.x, lane = tid & 31, wid = tid >> 5;
    const int gi = lane >> 2, tg = lane & 3;
    const float scale = 0.088388347648318447f;

    // Q tile (plain loads, once)
    for (int f = tid; f < 2048; f += 256) {
        int r = f >> 4, c8 = f & 15;
        *(uint4*)(Qs + r*FQP + c8*8) =
            *(const uint4*)(QKV + (size_t)(b*SS + qt*128 + r) * QKVN + h*HDIM + c8*8);
    }

    auto load_kv = [&](int st, int kt) {
        const uint32_t kb = sbK + (uint32_t)st * (64*FQP*2);
        const uint32_t vb = sbV + (uint32_t)st * (64*FQP*2);
        #pragma unroll
        for (int u = 0; u < 4; u++) {
            int f = tid + u * 256;
            int r = f >> 4, c8 = f & 15;
            size_t base = (size_t)(b*SS + kt*64 + r) * QKVN + kvh * HDIM;
            cp16(kb + (uint32_t)(r * (FQP*2) + c8 * 16), QKV + base + 2048 + c8*8);
            cp16(vb + (uint32_t)(r * (FQP*2) + c8 * 16), QKV + base + 2304 + c8*8);
        }
        cp_commit();
    };

    float oacc[16][4];
    #pragma unroll
    for (int i = 0; i < 16; i++)
        #pragma unroll
        for (int e = 0; e < 4; e++) oacc[i][e] = 0.f;
    float mrow[2] = {-1e30f, -1e30f}, lrow[2] = {0.f, 0.f};

    const int r0 = wid*16 + gi;
    const int kmax = 2*qt + 2;

    load_kv(0, 0);

    for (int kt = 0; kt < kmax; kt++) {
        __syncthreads();                       // stage (kt+1)&1 consumers done
        if (kt + 1 < kmax) {
            load_kv((kt + 1) & 1, kt + 1);
            asm volatile("cp.async.wait_group 1;" ::: "memory");
        } else {
            asm volatile("cp.async.wait_group 0;" ::: "memory");
        }
        __syncthreads();

        if (kt*64 > qt*128 + wid*16 + 15) continue;

        const __half* Ks = Kst + (kt & 1) * 64*FQP;
        const __half* Vs = Vst + (kt & 1) * 64*FQP;

        float sa[8][4];
        #pragma unroll
        for (int nt = 0; nt < 8; nt++)
            #pragma unroll
            for (int e = 0; e < 4; e++) sa[nt][e] = 0.f;
        #pragma unroll
        for (int ks = 0; ks < 8; ks++) {
            const int k0 = ks*16 + 2*tg;
            uint32_t a[4];
            a[0] = *(const uint32_t*)(Qs + r0*FQP + k0);
            a[1] = *(const uint32_t*)(Qs + (r0+8)*FQP + k0);
            a[2] = *(const uint32_t*)(Qs + r0*FQP + k0 + 8);
            a[3] = *(const uint32_t*)(Qs + (r0+8)*FQP + k0 + 8);
            #pragma unroll
            for (int nt = 0; nt < 8; nt++) {
                const int n = nt*8 + gi;
                uint32_t bb[2];
                bb[0] = *(const uint32_t*)(Ks + n*FQP + k0);
                bb[1] = *(const uint32_t*)(Ks + n*FQP + k0 + 8);
                mma_f16(sa[nt], a, bb);
            }
        }
        #pragma unroll
        for (int nt = 0; nt < 8; nt++)
            #pragma unroll
            for (int e = 0; e < 4; e++) sa[nt][e] *= scale;
        if (kt >= 2*qt) {
            const int qr0 = qt*128 + r0, qr1 = qr0 + 8;
            #pragma unroll
            for (int nt = 0; nt < 8; nt++) {
                int kc = kt*64 + nt*8 + 2*tg;
                if (kc     > qr0) sa[nt][0] = -1e30f;
                if (kc + 1 > qr0) sa[nt][1] = -1e30f;
                if (kc     > qr1) sa[nt][2] = -1e30f;
                if (kc + 1 > qr1) sa[nt][3] = -1e30f;
            }
        }

        float mx0 = -1e30f, mx1 = -1e30f;
        #pragma unroll
        for (int nt = 0; nt < 8; nt++) {
            mx0 = fmaxf(mx0, fmaxf(sa[nt][0], sa[nt][1]));
            mx1 = fmaxf(mx1, fmaxf(sa[nt][2], sa[nt][3]));
        }
        mx0 = fmaxf(mx0, __shfl_xor_sync(0xffffffffu, mx0, 1));
        mx0 = fmaxf(mx0, __shfl_xor_sync(0xffffffffu, mx0, 2));
        mx1 = fmaxf(mx1, __shfl_xor_sync(0xffffffffu, mx1, 1));
        mx1 = fmaxf(mx1, __shfl_xor_sync(0xffffffffu, mx1, 2));
        const float mn0 = fmaxf(mrow[0], mx0), mn1 = fmaxf(mrow[1], mx1);
        const float cr0 = __expf(mrow[0] - mn0), cr1 = __expf(mrow[1] - mn1);
        float s0 = 0.f, s1 = 0.f;
        #pragma unroll
        for (int nt = 0; nt < 8; nt++) {
            __half2 p0 = __floats2half2_rn(__expf(sa[nt][0] - mn0), __expf(sa[nt][1] - mn0));
            __half2 p1 = __floats2half2_rn(__expf(sa[nt][2] - mn1), __expf(sa[nt][3] - mn1));
            float2 p0f = __half22float2(p0), p1f = __half22float2(p1);
            s0 += p0f.x + p0f.y;
            s1 += p1f.x + p1f.y;
            *(__half2*)(Ps + r0*FPP + nt*8 + 2*tg)     = p0;
            *(__half2*)(Ps + (r0+8)*FPP + nt*8 + 2*tg) = p1;
        }
        s0 += __shfl_xor_sync(0xffffffffu, s0, 1);
        s0 += __shfl_xor_sync(0xffffffffu, s0, 2);
        s1 += __shfl_xor_sync(0xffffffffu, s1, 1);
        s1 += __shfl_xor_sync(0xffffffffu, s1, 2);
        lrow[0] = lrow[0]*cr0 + s0;
        lrow[1] = lrow[1]*cr1 + s1;
        mrow[0] = mn0; mrow[1] = mn1;
        #pragma unroll
        for (int nt = 0; nt < 16; nt++) {
            oacc[nt][0] *= cr0; oacc[nt][1] *= cr0;
            oacc[nt][2] *= cr1; oacc[nt][3] *= cr1;
        }
        __syncwarp();

        #pragma unroll
        for (int ks = 0; ks < 4; ks++) {
            const int k0 = ks*16 + 2*tg;
            uint32_t a[4];
            a[0] = *(const uint32_t*)(Ps + r0*FPP + k0);
            a[1] = *(const uint32_t*)(Ps + (r0+8)*FPP + k0);
            a[2] = *(const uint32_t*)(Ps + r0*FPP + k0 + 8);
            a[3] = *(const uint32_t*)(Ps + (r0+8)*FPP + k0 + 8);
            #pragma unroll
            for (int ntp = 0; ntp < 8; ntp++) {
                int kvrow = ks*16 + (lane & 15);
                int dcol  = (ntp*2 + (lane >> 4)) * 8;
                uint32_t addr = smem_u32(Vs + kvrow*FQP + dcol);
                uint32_t b0, b1, b2, b3;
                asm volatile(
                    "ldmatrix.sync.aligned.m8n8.x4.trans.shared.b16 {%0,%1,%2,%3}, [%4];"
                    : "=r"(b0), "=r"(b1), "=r"(b2), "=r"(b3) : "r"(addr));
                uint32_t bb0[2] = {b0, b1}, bb1[2] = {b2, b3};
                mma_f16(oacc[2*ntp],     a, bb0);
                mma_f16(oacc[2*ntp + 1], a, bb1);
            }
        }
    }

    const float inv0 = 1.0f / lrow[0], inv1 = 1.0f / lrow[1];
    __half* op0 = O + (size_t)(b*SS + qt*128 + r0)     * DD + h*HDIM + 2*tg;
    __half* op1 = O + (size_t)(b*SS + qt*128 + r0 + 8) * DD + h*HDIM + 2*tg;
    #pragma unroll
    for (int nt = 0; nt < 16; nt++) {
        *(__half2*)(op0 + nt*8) = __floats2half2_rn(oacc[nt][0]*inv0, oacc[nt][1]*inv0);
        *(__half2*)(op1 + nt*8) = __floats2half2_rn(oacc[nt][2]*inv1, oacc[nt][3]*inv1);
    }
}

// ---------------- launch ----------------
extern "C" void kernel_launch(void* const* d_in, const int* in_sizes, int n_in,
                              void* d_out, int out_size)
{
    (void)in_sizes; (void)n_in; (void)out_size;
    const float* x   = (const float*)d_in[0];
    const float* ln1 = (const float*)d_in[2];
    const float* wq  = (const float*)d_in[3];
    const float* bq  = (const float*)d_in[4];
    const float* wk  = (const float*)d_in[5];
    const float* bk  = (const float*)d_in[6];
    const float* wv  = (const float*)d_in[7];
    const float* bv  = (const float*)d_in[8];
    const float* wo  = (const float*)d_in[9];
    const float* ln2 = (const float*)d_in[10];
    const float* wg  = (const float*)d_in[11];
    const float* wu  = (const float*)d_in[12];
    const float* wd  = (const float*)d_in[13];
    float* out = (float*)d_out;

    __half *h, *qkv, *attn, *g, *act;
    __half *rwqkv, *rwo, *rwgu, *rwd;
    float *h2, *bqkv;
    cudaGetSymbolAddress((void**)&h,     g_h);
    cudaGetSymbolAddress((void**)&qkv,   g_qkv);
    cudaGetSymbolAddress((void**)&attn,  g_attn);
    cudaGetSymbolAddress((void**)&h2,    g_h2);
    cudaGetSymbolAddress((void**)&g,     g_g);
    cudaGetSymbolAddress((void**)&act,   g_act);
    cudaGetSymbolAddress((void**)&rwqkv, g_wqkv);
    cudaGetSymbolAddress((void**)&rwo,   g_wo);
    cudaGetSymbolAddress((void**)&rwgu,  g_wgu);
    cudaGetSymbolAddress((void**)&rwd,   g_wd);
    cudaGetSymbolAddress((void**)&bqkv,  g_bqkv);

    cudaFuncSetAttribute((const void*)hgemm_kernel<1,__half>, cudaFuncAttributeMaxDynamicSharedMemorySize, GEMM_SMEM);
    cudaFuncSetAttribute((const void*)hgemm_kernel<2,float>,  cudaFuncAttributeMaxDynamicSharedMemorySize, GEMM_SMEM);
    cudaFuncSetAttribute((const void*)hgemm_kernel<3,__half>, cudaFuncAttributeMaxDynamicSharedMemorySize, GEMM_SMEM);
    cudaFuncSetAttribute((const void*)flash_mma_kernel, cudaFuncAttributeMaxDynamicSharedMemorySize, FA_SMEM);

    // 0. weights -> fp16
    f2h_kernel<<<(DD*DD/4)/256, 256>>>(wq, rwqkv);
    f2h_kernel<<<(256*DD/4)/256, 256>>>(wk, rwqkv + 2048*DD);
    f2h_kernel<<<(256*DD/4)/256, 256>>>(wv, rwqkv + 2304*DD);
    f2h_kernel<<<(DD*DD/4)/256, 256>>>(wo, rwo);
    f2h_ilv_kernel<<<(II*DD/4)/256, 256>>>(wg, wu, rwgu);
    f2h_kernel<<<(DD*II/4)/256, 256>>>(wd, rwd);
    bias_concat_kernel<<<10, 256>>>(bq, bk, bv, bqkv);

    // 1. h = rmsnorm(x, ln1) -> half
    rmsnorm_kernel<<<MM, 256>>>(x, ln1, h);

    // 2. fused qkv projection (+bias)
    hgemm_kernel<1,__half><<<dim3(QKVN/128, MM/256), 256, GEMM_SMEM>>>(h, rwqkv, bqkv, qkv, MM, QKVN, DD);

    // 3. RoPE
    rope_kernel<<<(MM*HH*64)/256, 256>>>(qkv, HH, 0);
    rope_kernel<<<(MM*KVH*64)/256, 256>>>(qkv, KVH, 2048);

    // 4. attention
    flash_mma_kernel<<<dim3(SS/128, BB*HH), 256, FA_SMEM>>>(qkv, attn);

    // 5. h2 = x + attn @ wo^T (fp32)
    hgemm_kernel<2,float><<<dim3(DD/128, MM/256), 256, GEMM_SMEM>>>(attn, rwo, x, h2, MM, DD, DD);

    // 6. g = rmsnorm(h2, ln2) -> half
    rmsnorm_kernel<<<MM, 256>>>(h2, ln2, g);

    // 7. fused MLP gate/up + silu: act = silu(g@wg^T) * (g@wu^T)
    hgemm_kernel<3,__half><<<dim3(2*II/128, MM/256), 256, GEMM_SMEM>>>(g, rwgu, nullptr, act, MM, II, DD);

    // 8. out = h2 + act @ wd^T (fp32)
    hgemm_kernel<2,float><<<dim3(DD/128, MM/256), 256, GEMM_SMEM>>>(act, rwd, h2, out, MM, DD, II);
}